// round 5
// baseline (speedup 1.0000x reference)
#include <cuda_runtime.h>
#include <math.h>

#define BDIM 1024
#define LDIM 80
#define EDIM 256
#define DDIM 256
#define TDIM 20
#define NSPECIAL 4
#define NSYMB 100

// ---------------- device state (no allocation allowed) ----------------
__device__ float g_emb[(size_t)TDIM * BDIM * DDIM];   // [T,B,D]
__device__ float g_h0a[BDIM * DDIM];
__device__ float g_h0b[BDIM * DDIM];
__device__ float g_h1a[BDIM * DDIM];
__device__ float g_h1b[BDIM * DDIM];
__device__ float g_c0[BDIM * DDIM];
__device__ float g_c1[BDIM * DDIM];
__device__ float g_xc[BDIM * (DDIM + EDIM)];          // [B, 512] concat(e, applied)
__device__ float g_comb[BDIM * DDIM];
__device__ float g_z[BDIM * DDIM];                    // pre-log-softmax logits

// buffer selector (avoids any host-side symbol-address API)
#define SEL_XC   0
#define SEL_COMB 1
#define SEL_H0A  2
#define SEL_H0B  3
#define SEL_H1A  4
#define SEL_H1B  5
#define SEL_C0   6
#define SEL_C1   7
#define SEL_Z    8

__device__ __forceinline__ float* buf_ptr(int s) {
    switch (s) {
        case SEL_XC:   return g_xc;
        case SEL_COMB: return g_comb;
        case SEL_H0A:  return g_h0a;
        case SEL_H0B:  return g_h0b;
        case SEL_H1A:  return g_h1a;
        case SEL_H1B:  return g_h1b;
        case SEL_C0:   return g_c0;
        case SEL_C1:   return g_c1;
        case SEL_Z:    return g_z;
    }
    return nullptr;
}

// ---------------- embedding precompute: emb[t,b,d] ----------------
__global__ void embed_kernel(const int* __restrict__ tgt,
                             const float* __restrict__ common,
                             const float* __restrict__ syms) {
    int idx = blockIdx.x * 256 + threadIdx.x;       // over T*B*D
    int d  = idx & (DDIM - 1);
    int tb = idx >> 8;
    int t  = tb >> 10;                              // B = 1024
    int b  = tb & (BDIM - 1);
    int s  = tgt[b * TDIM + t];
    float v;
    if (s < NSPECIAL) {
        int si = s < 0 ? 0 : s;
        v = common[si * DDIM + d];
    } else {
        int si = s - NSPECIAL;
        if (si > NSYMB - 1) si = NSYMB - 1;
        v = syms[((size_t)b * NSYMB + si) * DDIM + d];
    }
    g_emb[idx] = v;
}

__global__ void zero_state_kernel() {
    int i = blockIdx.x * 256 + threadIdx.x;
    g_h0a[i] = 0.f; g_h0b[i] = 0.f;
    g_h1a[i] = 0.f; g_h1b[i] = 0.f;
    g_c0[i]  = 0.f; g_c1[i]  = 0.f;
}

// ---------------- fused attention: scores + softmax + context ----------------
// one CTA per batch row b. 256 threads = 8 warps.
__global__ __launch_bounds__(256) void attn_kernel(
    int t, int h1_sel,
    const float* __restrict__ enc,       // [B,L,E]
    const float* __restrict__ W_attn,    // [L, 2D]
    const float* __restrict__ b_attn)    // [L]
{
    int b   = blockIdx.x;
    int tid = threadIdx.x;
    __shared__ float eh[2 * DDIM];
    __shared__ float ap[LDIM];

    const float* h1 = buf_ptr(h1_sel);
    eh[tid]        = g_emb[((size_t)t * BDIM + b) * DDIM + tid];
    eh[DDIM + tid] = h1[b * DDIM + tid];
    __syncthreads();

    int warp = tid >> 5, lane = tid & 31;
    // 80 dot products of length 512; warp-parallel, coalesced W_attn reads
    for (int l = warp; l < LDIM; l += 8) {
        const float* wr = W_attn + l * (2 * DDIM);
        float s = 0.f;
        #pragma unroll 4
        for (int k = lane; k < 2 * DDIM; k += 32) s = fmaf(wr[k], eh[k], s);
        #pragma unroll
        for (int o = 16; o; o >>= 1) s += __shfl_xor_sync(0xffffffffu, s, o);
        if (lane == 0) ap[l] = s + b_attn[l];
    }
    __syncthreads();

    // softmax over 80 (warp 0)
    if (warp == 0) {
        float v0 = ap[lane], v1 = ap[lane + 32];
        float v2 = (lane < LDIM - 64) ? ap[lane + 64] : -1e30f;
        float m = fmaxf(fmaxf(v0, v1), v2);
        #pragma unroll
        for (int o = 16; o; o >>= 1) m = fmaxf(m, __shfl_xor_sync(0xffffffffu, m, o));
        float e0 = __expf(v0 - m), e1 = __expf(v1 - m);
        float e2 = (lane < LDIM - 64) ? __expf(v2 - m) : 0.f;
        float ssum = e0 + e1 + e2;
        #pragma unroll
        for (int o = 16; o; o >>= 1) ssum += __shfl_xor_sync(0xffffffffu, ssum, o);
        float inv = 1.f / ssum;
        ap[lane] = e0 * inv;
        ap[lane + 32] = e1 * inv;
        if (lane < LDIM - 64) ap[lane + 64] = e2 * inv;
    }
    __syncthreads();

    // context: applied[d] = sum_l ap[l] * enc[b,l,d]   (coalesced across d)
    float acc = 0.f;
    const float* eb = enc + (size_t)b * LDIM * EDIM + tid;
    #pragma unroll 8
    for (int l = 0; l < LDIM; l++) acc = fmaf(ap[l], eb[(size_t)l * EDIM], acc);

    g_xc[b * (DDIM + EDIM) + tid]        = eh[tid];   // e
    g_xc[b * (DDIM + EDIM) + DDIM + tid] = acc;       // applied
}

// ---- tiled GEMM: C = A1@W1^T (+ A2@W2^T) + biases; epilogue plain/relu/LSTM ----
// A: [M,K] row-major (scratch via selector), W: [N,K] row-major (input ptr).
// mode: 0 = plain store, 1 = relu store, 2 = fused LSTM cell.
// mode 2 uses column interleave: logical col q -> weight row (q&3)*256 + (q>>2),
// so each thread's 4 n-accumulators are gates i,f,g,o of hidden unit j=(q>>2).
#define BM 64
#define BN 64
#define BK 16

__global__ __launch_bounds__(256) void gemm_dual_kernel(
    int a1_sel, const float* __restrict__ W1, int K1,
    int a2_sel, const float* __restrict__ W2, int K2,
    const float* __restrict__ bias1, const float* __restrict__ bias2,
    int out_sel, int N, int mode, int c_sel, int hn_sel)
{
    __shared__ __align__(16) float As[BK][BM + 4];
    __shared__ __align__(16) float Ws[BK][BN + 4];
    int tid = threadIdx.x;
    int tx = tid & 15, ty = tid >> 4;
    int m0 = blockIdx.y * BM, n0 = blockIdx.x * BN;
    int lrow = tid >> 2;             // 0..63
    int lk   = (tid & 3) << 2;       // 0,4,8,12
    int q    = n0 + lrow;
    int wrow = (mode == 2) ? (((q & 3) << 8) | (q >> 2)) : q;
    float acc[4][4] = {};

    for (int phase = 0; phase < 2; phase++) {
        const float* A = buf_ptr(phase ? a2_sel : a1_sel);
        const float* W = phase ? W2 : W1;
        int K = phase ? K2 : K1;
        if (A == nullptr) continue;
        for (int k0 = 0; k0 < K; k0 += BK) {
            float4 av = *(const float4*)(A + (size_t)(m0 + lrow) * K + k0 + lk);
            float4 wv = *(const float4*)(W + (size_t)wrow * K + k0 + lk);
            __syncthreads();
            As[lk + 0][lrow] = av.x; As[lk + 1][lrow] = av.y;
            As[lk + 2][lrow] = av.z; As[lk + 3][lrow] = av.w;
            Ws[lk + 0][lrow] = wv.x; Ws[lk + 1][lrow] = wv.y;
            Ws[lk + 2][lrow] = wv.z; Ws[lk + 3][lrow] = wv.w;
            __syncthreads();
            #pragma unroll
            for (int kk = 0; kk < BK; kk++) {
                float4 a = *(const float4*)(&As[kk][ty << 2]);
                float4 w = *(const float4*)(&Ws[kk][tx << 2]);
                acc[0][0] = fmaf(a.x, w.x, acc[0][0]);
                acc[0][1] = fmaf(a.x, w.y, acc[0][1]);
                acc[0][2] = fmaf(a.x, w.z, acc[0][2]);
                acc[0][3] = fmaf(a.x, w.w, acc[0][3]);
                acc[1][0] = fmaf(a.y, w.x, acc[1][0]);
                acc[1][1] = fmaf(a.y, w.y, acc[1][1]);
                acc[1][2] = fmaf(a.y, w.z, acc[1][2]);
                acc[1][3] = fmaf(a.y, w.w, acc[1][3]);
                acc[2][0] = fmaf(a.z, w.x, acc[2][0]);
                acc[2][1] = fmaf(a.z, w.y, acc[2][1]);
                acc[2][2] = fmaf(a.z, w.z, acc[2][2]);
                acc[2][3] = fmaf(a.z, w.w, acc[2][3]);
                acc[3][0] = fmaf(a.w, w.x, acc[3][0]);
                acc[3][1] = fmaf(a.w, w.y, acc[3][1]);
                acc[3][2] = fmaf(a.w, w.z, acc[3][2]);
                acc[3][3] = fmaf(a.w, w.w, acc[3][3]);
            }
        }
    }

    if (mode == 2) {
        // fused LSTM cell: acc[i][0..3] = gates i,f,g,o for unit j
        float* c = buf_ptr(c_sel);
        float* h = buf_ptr(hn_sel);
        int j = (n0 >> 2) + tx;
        float bi = bias1[j]            + bias2[j];
        float bf = bias1[DDIM + j]     + bias2[DDIM + j];
        float bg = bias1[2 * DDIM + j] + bias2[2 * DDIM + j];
        float bo = bias1[3 * DDIM + j] + bias2[3 * DDIM + j];
        #pragma unroll
        for (int i = 0; i < 4; i++) {
            int m = m0 + (ty << 2) + i;
            float gi = acc[i][0] + bi;
            float gf = acc[i][1] + bf;
            float gg = acc[i][2] + bg;
            float go = acc[i][3] + bo;
            float si = 1.f / (1.f + __expf(-gi));
            float sf = 1.f / (1.f + __expf(-gf));
            float so = 1.f / (1.f + __expf(-go));
            float tg = tanhf(gg);
            int idx = m * DDIM + j;
            float cc = sf * c[idx] + si * tg;
            c[idx] = cc;
            h[idx] = so * tanhf(cc);
        }
    } else {
        float* C = buf_ptr(out_sel);
        #pragma unroll
        for (int i = 0; i < 4; i++) {
            int m = m0 + (ty << 2) + i;
            #pragma unroll
            for (int j = 0; j < 4; j++) {
                int n = n0 + (tx << 2) + j;
                float v = acc[i][j];
                if (bias1) v += bias1[n];
                if (mode == 1) v = fmaxf(v, 0.f);
                C[(size_t)m * N + n] = v;
            }
        }
    }
}

// ---------------- log-softmax over 256, write to out[t] ----------------
__global__ __launch_bounds__(256) void logsoftmax_kernel(int t, float* __restrict__ out) {
    int b = blockIdx.x, tid = threadIdx.x;
    __shared__ float sm[256];
    float v = g_z[b * DDIM + tid];
    sm[tid] = v; __syncthreads();
    #pragma unroll
    for (int o = 128; o; o >>= 1) { if (tid < o) sm[tid] = fmaxf(sm[tid], sm[tid + o]); __syncthreads(); }
    float mx = sm[0]; __syncthreads();
    float e = __expf(v - mx);
    sm[tid] = e; __syncthreads();
    #pragma unroll
    for (int o = 128; o; o >>= 1) { if (tid < o) sm[tid] += sm[tid + o]; __syncthreads(); }
    float lse = __logf(sm[0]) + mx;
    out[((size_t)t * BDIM + b) * DDIM + tid] = v - lse;
}

// ---------------- launch ----------------
extern "C" void kernel_launch(void* const* d_in, const int* in_sizes, int n_in,
                              void* d_out, int out_size) {
    (void)in_sizes; (void)n_in; (void)out_size;
    const float* enc    = (const float*)d_in[0];
    const float* syms   = (const float*)d_in[1];
    const int*   tgt    = (const int*)d_in[2];
    const float* common = (const float*)d_in[3];
    const float* W_attn = (const float*)d_in[4];
    const float* b_attn = (const float*)d_in[5];
    const float* W_comb = (const float*)d_in[6];
    const float* b_comb = (const float*)d_in[7];
    const float* Wih0   = (const float*)d_in[8];
    const float* Whh0   = (const float*)d_in[9];
    const float* bih0   = (const float*)d_in[10];
    const float* bhh0   = (const float*)d_in[11];
    const float* Wih1   = (const float*)d_in[12];
    const float* Whh1   = (const float*)d_in[13];
    const float* bih1   = (const float*)d_in[14];
    const float* bhh1   = (const float*)d_in[15];
    const float* W_out  = (const float*)d_in[16];
    const float* b_out  = (const float*)d_in[17];
    float* out = (float*)d_out;

    embed_kernel<<<(TDIM * BDIM * DDIM) / 256, 256>>>(tgt, common, syms);
    zero_state_kernel<<<(BDIM * DDIM) / 256, 256>>>();

    int h0_cur = SEL_H0A, h0_nxt = SEL_H0B;
    int h1_cur = SEL_H1A, h1_nxt = SEL_H1B;

    for (int t = 0; t < TDIM; t++) {
        attn_kernel<<<BDIM, 256>>>(t, h1_cur, enc, W_attn, b_attn);
        // comb = relu(xc @ W_comb^T + b_comb)   [1024 x 256], K=512
        gemm_dual_kernel<<<dim3(DDIM / BN, BDIM / BM), 256>>>(
            SEL_XC, W_comb, DDIM + EDIM, -1, nullptr, 0,
            b_comb, nullptr, SEL_COMB, DDIM, 1, -1, -1);
        // layer 0: gates = comb@Wih0^T + h0_cur@Whh0^T + b; fused cell -> h0_nxt, c0
        gemm_dual_kernel<<<dim3(4 * DDIM / BN, BDIM / BM), 256>>>(
            SEL_COMB, Wih0, DDIM, h0_cur, Whh0, DDIM,
            bih0, bhh0, -1, 4 * DDIM, 2, SEL_C0, h0_nxt);
        // layer 1: gates = h0_nxt@Wih1^T + h1_cur@Whh1^T + b; fused cell -> h1_nxt, c1
        gemm_dual_kernel<<<dim3(4 * DDIM / BN, BDIM / BM), 256>>>(
            h0_nxt, Wih1, DDIM, h1_cur, Whh1, DDIM,
            bih1, bhh1, -1, 4 * DDIM, 2, SEL_C1, h1_nxt);
        // z = h1_nxt @ W_out^T + b_out
        gemm_dual_kernel<<<dim3(DDIM / BN, BDIM / BM), 256>>>(
            h1_nxt, W_out, EDIM, -1, nullptr, 0,
            b_out, nullptr, SEL_Z, DDIM, 0, -1, -1);
        logsoftmax_kernel<<<BDIM, 256>>>(t, out);

        int tmp;
        tmp = h0_cur; h0_cur = h0_nxt; h0_nxt = tmp;
        tmp = h1_cur; h1_cur = h1_nxt; h1_nxt = tmp;
    }
}

// round 7
// speedup vs baseline: 1.2938x; 1.2938x over previous
#include <cuda_runtime.h>
#include <cuda_bf16.h>
#include <math.h>
#include <stdint.h>

#define BDIM 1024
#define LDIM 80
#define EDIM 256
#define DDIM 256
#define TDIM 20
#define NSPECIAL 4
#define NSYMB 100

// ---------------- device state (no allocation allowed) ----------------
__device__ float g_emb[(size_t)TDIM * BDIM * DDIM];   // [T,B,D]
__device__ float g_h0a[BDIM * DDIM];
__device__ float g_h0b[BDIM * DDIM];
__device__ float g_h1a[BDIM * DDIM];
__device__ float g_h1b[BDIM * DDIM];
__device__ float g_c0[BDIM * DDIM];
__device__ float g_c1[BDIM * DDIM];
__device__ float g_xc[BDIM * (DDIM + EDIM)];          // [B, 512]
__device__ float g_comb[BDIM * DDIM];
__device__ float g_z[BDIM * DDIM];

// pre-split weights: plain row-major [N][Ktot] bf16 hi/lo
__device__ __nv_bfloat16 g_w0hi[1024 * 512];
__device__ __nv_bfloat16 g_w0lo[1024 * 512];
__device__ __nv_bfloat16 g_w1hi[1024 * 512];
__device__ __nv_bfloat16 g_w1lo[1024 * 512];
__device__ __nv_bfloat16 g_wchi[256 * 512];
__device__ __nv_bfloat16 g_wclo[256 * 512];
__device__ __nv_bfloat16 g_wohi[256 * 256];
__device__ __nv_bfloat16 g_wolo[256 * 256];

#define SEL_XC   0
#define SEL_COMB 1
#define SEL_H0A  2
#define SEL_H0B  3
#define SEL_H1A  4
#define SEL_H1B  5
#define SEL_C0   6
#define SEL_C1   7
#define SEL_Z    8
#define SEL_W0HI 9
#define SEL_W0LO 10
#define SEL_W1HI 11
#define SEL_W1LO 12
#define SEL_WCHI 13
#define SEL_WCLO 14
#define SEL_WOHI 15
#define SEL_WOLO 16

__device__ __forceinline__ float* buf_ptr(int s) {
    switch (s) {
        case SEL_XC:   return g_xc;
        case SEL_COMB: return g_comb;
        case SEL_H0A:  return g_h0a;
        case SEL_H0B:  return g_h0b;
        case SEL_H1A:  return g_h1a;
        case SEL_H1B:  return g_h1b;
        case SEL_C0:   return g_c0;
        case SEL_C1:   return g_c1;
        case SEL_Z:    return g_z;
    }
    return nullptr;
}
__device__ __forceinline__ __nv_bfloat16* wbuf_ptr(int s) {
    switch (s) {
        case SEL_W0HI: return g_w0hi;
        case SEL_W0LO: return g_w0lo;
        case SEL_W1HI: return g_w1hi;
        case SEL_W1LO: return g_w1lo;
        case SEL_WCHI: return g_wchi;
        case SEL_WCLO: return g_wclo;
        case SEL_WOHI: return g_wohi;
        case SEL_WOLO: return g_wolo;
    }
    return nullptr;
}

__device__ __forceinline__ uint32_t smem_u32(const void* p) {
    uint32_t a;
    asm("{ .reg .u64 t; cvta.to.shared.u64 t, %1; cvt.u32.u64 %0, t; }" : "=r"(a) : "l"(p));
    return a;
}

__device__ __forceinline__ void ldm_x4(uint32_t* r, uint32_t addr) {
    asm volatile("ldmatrix.sync.aligned.m8n8.x4.shared.b16 {%0,%1,%2,%3}, [%4];"
                 : "=r"(r[0]), "=r"(r[1]), "=r"(r[2]), "=r"(r[3]) : "r"(addr));
}
__device__ __forceinline__ void ldm_x2(uint32_t* r, uint32_t addr) {
    asm volatile("ldmatrix.sync.aligned.m8n8.x2.shared.b16 {%0,%1}, [%2];"
                 : "=r"(r[0]), "=r"(r[1]) : "r"(addr));
}
__device__ __forceinline__ void mma_bf16(float* d, const uint32_t* a, const uint32_t* b) {
    asm volatile(
        "mma.sync.aligned.m16n8k16.row.col.f32.bf16.bf16.f32 "
        "{%0,%1,%2,%3}, {%4,%5,%6,%7}, {%8,%9}, {%0,%1,%2,%3};"
        : "+f"(d[0]), "+f"(d[1]), "+f"(d[2]), "+f"(d[3])
        : "r"(a[0]), "r"(a[1]), "r"(a[2]), "r"(a[3]), "r"(b[0]), "r"(b[1]));
}

__device__ __forceinline__ void split2(float x, float y, uint32_t& hi, uint32_t& lo) {
    __nv_bfloat16 hx = __float2bfloat16(x);
    __nv_bfloat16 hy = __float2bfloat16(y);
    __nv_bfloat16 lx = __float2bfloat16(x - __bfloat162float(hx));
    __nv_bfloat16 ly = __float2bfloat16(y - __bfloat162float(hy));
    hi = (uint32_t)__bfloat16_as_ushort(hx) | ((uint32_t)__bfloat16_as_ushort(hy) << 16);
    lo = (uint32_t)__bfloat16_as_ushort(lx) | ((uint32_t)__bfloat16_as_ushort(ly) << 16);
}

// ---- weight pre-split: fp32 -> bf16 hi/lo, row-major [N][Ktot] ----
// optional K-concat (S1 k1 cols | S2 k2 cols) and gate-row interleave
// (new row n <- old row ((n&3)<<8)|(n>>2)).
__global__ void conv_w_kernel(const float* __restrict__ S1, int k1,
                              const float* __restrict__ S2, int k2,
                              int Ktot, int interleave, int hi_sel, int lo_sel) {
    int idx = blockIdx.x * 256 + threadIdx.x;   // over N*Ktot
    int n = idx / Ktot;
    int k = idx - n * Ktot;
    int rs = interleave ? (((n & 3) << 8) | (n >> 2)) : n;
    float x = (k < k1) ? S1[(size_t)rs * k1 + k] : S2[(size_t)rs * k2 + (k - k1)];
    __nv_bfloat16 h = __float2bfloat16(x);
    __nv_bfloat16 l = __float2bfloat16(x - __bfloat162float(h));
    wbuf_ptr(hi_sel)[idx] = h;
    wbuf_ptr(lo_sel)[idx] = l;
}

// ---------------- embedding / init ----------------
__global__ void embed_kernel(const int* __restrict__ tgt,
                             const float* __restrict__ common,
                             const float* __restrict__ syms) {
    int idx = blockIdx.x * 256 + threadIdx.x;
    int d  = idx & (DDIM - 1);
    int tb = idx >> 8;
    int t  = tb >> 10;
    int b  = tb & (BDIM - 1);
    int s  = tgt[b * TDIM + t];
    float v;
    if (s < NSPECIAL) {
        int si = s < 0 ? 0 : s;
        v = common[si * DDIM + d];
    } else {
        int si = s - NSPECIAL;
        if (si > NSYMB - 1) si = NSYMB - 1;
        v = syms[((size_t)b * NSYMB + si) * DDIM + d];
    }
    g_emb[idx] = v;
}

__global__ void zero_state_kernel() {
    int i = blockIdx.x * 256 + threadIdx.x;
    g_h0a[i] = 0.f; g_h0b[i] = 0.f;
    g_h1a[i] = 0.f; g_h1b[i] = 0.f;
    g_c0[i]  = 0.f; g_c1[i]  = 0.f;
}

// ---------------- fused attention ----------------
__global__ __launch_bounds__(256) void attn_kernel(
    int t, int h1_sel,
    const float* __restrict__ enc,
    const float* __restrict__ W_attn,
    const float* __restrict__ b_attn)
{
    int b   = blockIdx.x;
    int tid = threadIdx.x;
    __shared__ float eh[2 * DDIM];
    __shared__ float ap[LDIM];

    const float* h1 = buf_ptr(h1_sel);
    eh[tid]        = g_emb[((size_t)t * BDIM + b) * DDIM + tid];
    eh[DDIM + tid] = h1[b * DDIM + tid];
    __syncthreads();

    int warp = tid >> 5, lane = tid & 31;
    for (int l = warp; l < LDIM; l += 8) {
        const float* wr = W_attn + l * (2 * DDIM);
        float s = 0.f;
        #pragma unroll 4
        for (int k = lane; k < 2 * DDIM; k += 32) s = fmaf(wr[k], eh[k], s);
        #pragma unroll
        for (int o = 16; o; o >>= 1) s += __shfl_xor_sync(0xffffffffu, s, o);
        if (lane == 0) ap[l] = s + b_attn[l];
    }
    __syncthreads();

    if (warp == 0) {
        float v0 = ap[lane], v1 = ap[lane + 32];
        float v2 = (lane < LDIM - 64) ? ap[lane + 64] : -1e30f;
        float m = fmaxf(fmaxf(v0, v1), v2);
        #pragma unroll
        for (int o = 16; o; o >>= 1) m = fmaxf(m, __shfl_xor_sync(0xffffffffu, m, o));
        float e0 = __expf(v0 - m), e1 = __expf(v1 - m);
        float e2 = (lane < LDIM - 64) ? __expf(v2 - m) : 0.f;
        float ssum = e0 + e1 + e2;
        #pragma unroll
        for (int o = 16; o; o >>= 1) ssum += __shfl_xor_sync(0xffffffffu, ssum, o);
        float inv = 1.f / ssum;
        ap[lane] = e0 * inv;
        ap[lane + 32] = e1 * inv;
        if (lane < LDIM - 64) ap[lane + 64] = e2 * inv;
    }
    __syncthreads();

    float acc = 0.f;
    const float* eb = enc + (size_t)b * LDIM * EDIM + tid;
    #pragma unroll 8
    for (int l = 0; l < LDIM; l++) acc = fmaf(ap[l], eb[(size_t)l * EDIM], acc);

    g_xc[b * (DDIM + EDIM) + tid]        = eh[tid];
    g_xc[b * (DDIM + EDIM) + DDIM + tid] = acc;
}

// ---- HMMA GEMM: C[BMxBN tile] = A@W^T via bf16 hi/lo split (3 passes) ----
// A fp32 row-major (dual K-concat A1|A2), W pre-split bf16 hi/lo [N][Ktot].
// mode: 0 plain+bias, 1 relu+bias, 2 fused LSTM cell (interleaved gate cols).
#define BM 128
#define BN 64
#define KC 64
#define AST 72            // padded bf16 row stride in smem
#define GST 68            // epilogue float row stride
#define OFF_AHI 0
#define OFF_ALO 18432
#define OFF_BHI 36864
#define OFF_BLO 46080
#define GSM_TOTAL 55296

__global__ __launch_bounds__(256, 1)
void gemm_mma_kernel(int a1_sel, int a1_ld, int K1,
                     int a2_sel, int a2_ld, int Ktot,
                     int whi_sel, int wlo_sel,
                     const float* __restrict__ bias1, const float* __restrict__ bias2,
                     int out_sel, int ldc, int mode, int c_sel, int h_sel)
{
    extern __shared__ __align__(16) char sm[];
    uint32_t smb = smem_u32(sm);
    int tid = threadIdx.x, wid = tid >> 5, lane = tid & 31;
    int wm = (wid & 3) * 32;          // warp M offset (4 warps over 128)
    int wn = (wid >> 2) * 32;         // warp N offset (2 warps over 64)
    int m0 = blockIdx.y * BM;
    int n0 = blockIdx.x * BN;

    const float* A1 = buf_ptr(a1_sel);
    const float* A2 = buf_ptr(a2_sel);
    const __nv_bfloat16* whi = wbuf_ptr(whi_sel) + (size_t)n0 * Ktot;
    const __nv_bfloat16* wlo = wbuf_ptr(wlo_sel) + (size_t)n0 * Ktot;

    float acc[2][4][4];
    #pragma unroll
    for (int i = 0; i < 2; i++)
        #pragma unroll
        for (int j = 0; j < 4; j++)
            #pragma unroll
            for (int k = 0; k < 4; k++) acc[i][j][k] = 0.f;

    int nchunks = Ktot / KC;
    int arow = tid >> 1;              // A load: 2 threads/row
    int acb  = (tid & 1) * 32;        // col half
    int brow = tid >> 2;              // B load: 4 threads/row
    int bcb  = (tid & 3) * 16;

    for (int kc = 0; kc < nchunks; kc++) {
        int kg = kc * KC;
        // A: fp32 load, bf16 hi/lo split, padded smem store
        {
            const float* Ar = (kg < K1)
                ? A1 + (size_t)(m0 + arow) * a1_ld + kg + acb
                : A2 + (size_t)(m0 + arow) * a2_ld + (kg - K1) + acb;
            #pragma unroll
            for (int i = 0; i < 8; i++) {
                float4 v = *(const float4*)(Ar + i * 4);
                uint2 H, L;
                split2(v.x, v.y, H.x, L.x);
                split2(v.z, v.w, H.y, L.y);
                int off = (arow * AST + acb + i * 4) * 2;
                *(uint2*)(sm + OFF_AHI + off) = H;
                *(uint2*)(sm + OFF_ALO + off) = L;
            }
        }
        // B: straight bf16 copies into padded smem
        {
            size_t src = (size_t)brow * Ktot + kg + bcb;
            int off = (brow * AST + bcb) * 2;
            *(uint4*)(sm + OFF_BHI + off)      = *(const uint4*)(whi + src);
            *(uint4*)(sm + OFF_BHI + off + 16) = *(const uint4*)(whi + src + 8);
            *(uint4*)(sm + OFF_BLO + off)      = *(const uint4*)(wlo + src);
            *(uint4*)(sm + OFF_BLO + off + 16) = *(const uint4*)(wlo + src + 8);
        }
        __syncthreads();

        #pragma unroll
        for (int kk = 0; kk < 4; kk++) {
            int k0 = kk * 16;
            uint32_t ah[2][4], al[2][4], bh[4][2], bl[4][2];
            int ar = wm + (lane & 15);
            int ac = k0 + ((lane >> 4) << 3);
            #pragma unroll
            for (int mi = 0; mi < 2; mi++) {
                uint32_t ad = smb + (((ar + mi * 16) * AST + ac) << 1);
                ldm_x4(ah[mi], ad + OFF_AHI);
                ldm_x4(al[mi], ad + OFF_ALO);
            }
            int br = wn + (lane & 7);
            int bc = k0 + (((lane >> 3) & 1) << 3);
            #pragma unroll
            for (int ni = 0; ni < 4; ni++) {
                uint32_t bd = smb + (((br + ni * 8) * AST + bc) << 1);
                ldm_x2(bh[ni], bd + OFF_BHI);
                ldm_x2(bl[ni], bd + OFF_BLO);
            }
            #pragma unroll
            for (int mi = 0; mi < 2; mi++)
                #pragma unroll
                for (int ni = 0; ni < 4; ni++) {
                    mma_bf16(acc[mi][ni], ah[mi], bh[ni]);
                    mma_bf16(acc[mi][ni], ah[mi], bl[ni]);
                    mma_bf16(acc[mi][ni], al[mi], bh[ni]);
                }
        }
        __syncthreads();
    }

    // stage accumulators through smem (aliases A/B buffers)
    float* gbuf = (float*)sm;
    #pragma unroll
    for (int mi = 0; mi < 2; mi++)
        #pragma unroll
        for (int ni = 0; ni < 4; ni++) {
            int r = wm + mi * 16 + (lane >> 2);
            int cc = wn + ni * 8 + 2 * (lane & 3);
            *(float2*)&gbuf[r * GST + cc]       = make_float2(acc[mi][ni][0], acc[mi][ni][1]);
            *(float2*)&gbuf[(r + 8) * GST + cc] = make_float2(acc[mi][ni][2], acc[mi][ni][3]);
        }
    __syncthreads();

    if (mode == 2) {
        // BN=64 -> 16 hidden units per CTA, cols 4u..4u+3 = gates i,f,g,o
        float* cb = buf_ptr(c_sel);
        float* hb = buf_ptr(h_sel);
        #pragma unroll
        for (int i = 0; i < 8; i++) {
            int idx = tid + i * 256;          // over 128*16
            int m = idx >> 4, u = idx & 15;
            int j = (n0 >> 2) + u;
            float gi = gbuf[m * GST + 4 * u + 0] + bias1[j]       + bias2[j];
            float gf = gbuf[m * GST + 4 * u + 1] + bias1[256 + j] + bias2[256 + j];
            float gg = gbuf[m * GST + 4 * u + 2] + bias1[512 + j] + bias2[512 + j];
            float go = gbuf[m * GST + 4 * u + 3] + bias1[768 + j] + bias2[768 + j];
            float si = 1.f / (1.f + __expf(-gi));
            float sf = 1.f / (1.f + __expf(-gf));
            float so = 1.f / (1.f + __expf(-go));
            int gidx = (m0 + m) * DDIM + j;
            float ccv = sf * cb[gidx] + si * tanhf(gg);
            cb[gidx] = ccv;
            hb[gidx] = so * tanhf(ccv);
        }
    } else {
        float* C = buf_ptr(out_sel);
        #pragma unroll
        for (int i = 0; i < 8; i++) {
            int idx = tid + i * 256;          // over 128*16 float4s
            int m = idx >> 4, nq = (idx & 15) << 2;
            int n = n0 + nq;
            float4 v;
            v.x = gbuf[m * GST + nq + 0] + bias1[n + 0];
            v.y = gbuf[m * GST + nq + 1] + bias1[n + 1];
            v.z = gbuf[m * GST + nq + 2] + bias1[n + 2];
            v.w = gbuf[m * GST + nq + 3] + bias1[n + 3];
            if (mode == 1) {
                v.x = fmaxf(v.x, 0.f); v.y = fmaxf(v.y, 0.f);
                v.z = fmaxf(v.z, 0.f); v.w = fmaxf(v.w, 0.f);
            }
            *(float4*)(C + (size_t)(m0 + m) * ldc + n) = v;
        }
    }
}

// ---------------- log-softmax over 256 ----------------
__global__ __launch_bounds__(256) void logsoftmax_kernel(int t, float* __restrict__ out) {
    int b = blockIdx.x, tid = threadIdx.x;
    __shared__ float smr[256];
    float v = g_z[b * DDIM + tid];
    smr[tid] = v; __syncthreads();
    #pragma unroll
    for (int o = 128; o; o >>= 1) { if (tid < o) smr[tid] = fmaxf(smr[tid], smr[tid + o]); __syncthreads(); }
    float mx = smr[0]; __syncthreads();
    float e = __expf(v - mx);
    smr[tid] = e; __syncthreads();
    #pragma unroll
    for (int o = 128; o; o >>= 1) { if (tid < o) smr[tid] += smr[tid + o]; __syncthreads(); }
    float lse = __logf(smr[0]) + mx;
    out[((size_t)t * BDIM + b) * DDIM + tid] = v - lse;
}

// ---------------- launch ----------------
extern "C" void kernel_launch(void* const* d_in, const int* in_sizes, int n_in,
                              void* d_out, int out_size) {
    (void)in_sizes; (void)n_in; (void)out_size;
    const float* enc    = (const float*)d_in[0];
    const float* syms   = (const float*)d_in[1];
    const int*   tgt    = (const int*)d_in[2];
    const float* common = (const float*)d_in[3];
    const float* W_attn = (const float*)d_in[4];
    const float* b_attn = (const float*)d_in[5];
    const float* W_comb = (const float*)d_in[6];
    const float* b_comb = (const float*)d_in[7];
    const float* Wih0   = (const float*)d_in[8];
    const float* Whh0   = (const float*)d_in[9];
    const float* bih0   = (const float*)d_in[10];
    const float* bhh0   = (const float*)d_in[11];
    const float* Wih1   = (const float*)d_in[12];
    const float* Whh1   = (const float*)d_in[13];
    const float* bih1   = (const float*)d_in[14];
    const float* bhh1   = (const float*)d_in[15];
    const float* W_out  = (const float*)d_in[16];
    const float* b_out  = (const float*)d_in[17];
    float* out = (float*)d_out;

    cudaFuncSetAttribute(gemm_mma_kernel,
                         cudaFuncAttributeMaxDynamicSharedMemorySize, GSM_TOTAL);

    embed_kernel<<<(TDIM * BDIM * DDIM) / 256, 256>>>(tgt, common, syms);
    zero_state_kernel<<<(BDIM * DDIM) / 256, 256>>>();

    // weight pre-split (gates: interleaved rows, K-concat Wih|Whh)
    conv_w_kernel<<<(1024 * 512) / 256, 256>>>(Wih0, 256, Whh0, 256, 512, 1, SEL_W0HI, SEL_W0LO);
    conv_w_kernel<<<(1024 * 512) / 256, 256>>>(Wih1, 256, Whh1, 256, 512, 1, SEL_W1HI, SEL_W1LO);
    conv_w_kernel<<<(256 * 512) / 256, 256>>>(W_comb, 512, W_comb, 0, 512, 0, SEL_WCHI, SEL_WCLO);
    conv_w_kernel<<<(256 * 256) / 256, 256>>>(W_out, 256, W_out, 0, 256, 0, SEL_WOHI, SEL_WOLO);

    int h0_cur = SEL_H0A, h0_nxt = SEL_H0B;
    int h1_cur = SEL_H1A, h1_nxt = SEL_H1B;

    for (int t = 0; t < TDIM; t++) {
        attn_kernel<<<BDIM, 256>>>(t, h1_cur, enc, W_attn, b_attn);
        // comb = relu(xc @ W_comb^T + b_comb)   [1024x256], K=512
        gemm_mma_kernel<<<dim3(DDIM / BN, BDIM / BM), 256, GSM_TOTAL>>>(
            SEL_XC, 512, 512, SEL_XC, 512, 512,
            SEL_WCHI, SEL_WCLO, b_comb, nullptr, SEL_COMB, 256, 1, -1, -1);
        // layer 0 gates + fused cell
        gemm_mma_kernel<<<dim3(4 * DDIM / BN, BDIM / BM), 256, GSM_TOTAL>>>(
            SEL_COMB, 256, 256, h0_cur, 256, 512,
            SEL_W0HI, SEL_W0LO, bih0, bhh0, -1, 0, 2, SEL_C0, h0_nxt);
        // layer 1 gates + fused cell
        gemm_mma_kernel<<<dim3(4 * DDIM / BN, BDIM / BM), 256, GSM_TOTAL>>>(
            h0_nxt, 256, 256, h1_cur, 256, 512,
            SEL_W1HI, SEL_W1LO, bih1, bhh1, -1, 0, 2, SEL_C1, h1_nxt);
        // z = h1' @ W_out^T + b_out   [1024x256], K=256
        gemm_mma_kernel<<<dim3(DDIM / BN, BDIM / BM), 256, GSM_TOTAL>>>(
            h1_nxt, 256, 256, h1_nxt, 256, 256,
            SEL_WOHI, SEL_WOLO, b_out, nullptr, SEL_Z, 256, 0, -1, -1);
        logsoftmax_kernel<<<BDIM, 256>>>(t, out);

        int tmp;
        tmp = h0_cur; h0_cur = h0_nxt; h0_nxt = tmp;
        tmp = h1_cur; h1_cur = h1_nxt; h1_nxt = tmp;
    }
}

// round 9
// speedup vs baseline: 1.3193x; 1.0197x over previous
#include <cuda_runtime.h>
#include <cuda_bf16.h>
#include <math.h>
#include <stdint.h>

#define BDIM 1024
#define LDIM 80
#define EDIM 256
#define DDIM 256
#define TDIM 20
#define NSPECIAL 4
#define NSYMB 100

// ---------------- device state (no allocation allowed) ----------------
__device__ float g_emb[(size_t)TDIM * BDIM * DDIM];   // [T,B,D]
__device__ float g_h0a[BDIM * DDIM];
__device__ float g_h0b[BDIM * DDIM];
__device__ float g_h1a[BDIM * DDIM];
__device__ float g_h1b[BDIM * DDIM];
__device__ float g_c0[BDIM * DDIM];
__device__ float g_c1[BDIM * DDIM];
__device__ float g_xc[BDIM * (DDIM + EDIM)];          // [B, 512]
__device__ float g_comb[BDIM * DDIM];
__device__ float g_z[BDIM * DDIM];

// pre-split weights: plain row-major [N][Ktot] bf16 hi/lo
__device__ __nv_bfloat16 g_w0hi[1024 * 512];
__device__ __nv_bfloat16 g_w0lo[1024 * 512];
__device__ __nv_bfloat16 g_w1hi[1024 * 512];
__device__ __nv_bfloat16 g_w1lo[1024 * 512];
__device__ __nv_bfloat16 g_wchi[256 * 512];
__device__ __nv_bfloat16 g_wclo[256 * 512];
__device__ __nv_bfloat16 g_wohi[256 * 256];
__device__ __nv_bfloat16 g_wolo[256 * 256];

#define SEL_XC   0
#define SEL_COMB 1
#define SEL_H0A  2
#define SEL_H0B  3
#define SEL_H1A  4
#define SEL_H1B  5
#define SEL_C0   6
#define SEL_C1   7
#define SEL_Z    8
#define SEL_W0HI 9
#define SEL_W0LO 10
#define SEL_W1HI 11
#define SEL_W1LO 12
#define SEL_WCHI 13
#define SEL_WCLO 14
#define SEL_WOHI 15
#define SEL_WOLO 16

__device__ __forceinline__ float* buf_ptr(int s) {
    switch (s) {
        case SEL_XC:   return g_xc;
        case SEL_COMB: return g_comb;
        case SEL_H0A:  return g_h0a;
        case SEL_H0B:  return g_h0b;
        case SEL_H1A:  return g_h1a;
        case SEL_H1B:  return g_h1b;
        case SEL_C0:   return g_c0;
        case SEL_C1:   return g_c1;
        case SEL_Z:    return g_z;
    }
    return nullptr;
}
__device__ __forceinline__ __nv_bfloat16* wbuf_ptr(int s) {
    switch (s) {
        case SEL_W0HI: return g_w0hi;
        case SEL_W0LO: return g_w0lo;
        case SEL_W1HI: return g_w1hi;
        case SEL_W1LO: return g_w1lo;
        case SEL_WCHI: return g_wchi;
        case SEL_WCLO: return g_wclo;
        case SEL_WOHI: return g_wohi;
        case SEL_WOLO: return g_wolo;
    }
    return nullptr;
}

__device__ __forceinline__ uint32_t smem_u32(const void* p) {
    uint32_t a;
    asm("{ .reg .u64 t; cvta.to.shared.u64 t, %1; cvt.u32.u64 %0, t; }" : "=r"(a) : "l"(p));
    return a;
}

__device__ __forceinline__ void ldm_x4(uint32_t* r, uint32_t addr) {
    asm volatile("ldmatrix.sync.aligned.m8n8.x4.shared.b16 {%0,%1,%2,%3}, [%4];"
                 : "=r"(r[0]), "=r"(r[1]), "=r"(r[2]), "=r"(r[3]) : "r"(addr));
}
__device__ __forceinline__ void ldm_x2(uint32_t* r, uint32_t addr) {
    asm volatile("ldmatrix.sync.aligned.m8n8.x2.shared.b16 {%0,%1}, [%2];"
                 : "=r"(r[0]), "=r"(r[1]) : "r"(addr));
}
__device__ __forceinline__ void mma_bf16(float* d, const uint32_t* a, const uint32_t* b) {
    asm volatile(
        "mma.sync.aligned.m16n8k16.row.col.f32.bf16.bf16.f32 "
        "{%0,%1,%2,%3}, {%4,%5,%6,%7}, {%8,%9}, {%0,%1,%2,%3};"
        : "+f"(d[0]), "+f"(d[1]), "+f"(d[2]), "+f"(d[3])
        : "r"(a[0]), "r"(a[1]), "r"(a[2]), "r"(a[3]), "r"(b[0]), "r"(b[1]));
}

__device__ __forceinline__ void split2(float x, float y, uint32_t& hi, uint32_t& lo) {
    __nv_bfloat16 hx = __float2bfloat16(x);
    __nv_bfloat16 hy = __float2bfloat16(y);
    __nv_bfloat16 lx = __float2bfloat16(x - __bfloat162float(hx));
    __nv_bfloat16 ly = __float2bfloat16(y - __bfloat162float(hy));
    hi = (uint32_t)__bfloat16_as_ushort(hx) | ((uint32_t)__bfloat16_as_ushort(hy) << 16);
    lo = (uint32_t)__bfloat16_as_ushort(lx) | ((uint32_t)__bfloat16_as_ushort(ly) << 16);
}

// ---- weight pre-split: fp32 -> bf16 hi/lo, row-major [N][Ktot] ----
__global__ void conv_w_kernel(const float* __restrict__ S1, int k1,
                              const float* __restrict__ S2, int k2,
                              int Ktot, int interleave, int hi_sel, int lo_sel) {
    int idx = blockIdx.x * 256 + threadIdx.x;   // over N*Ktot
    int n = idx / Ktot;
    int k = idx - n * Ktot;
    int rs = interleave ? (((n & 3) << 8) | (n >> 2)) : n;
    float x = (k < k1) ? S1[(size_t)rs * k1 + k] : S2[(size_t)rs * k2 + (k - k1)];
    __nv_bfloat16 h = __float2bfloat16(x);
    __nv_bfloat16 l = __float2bfloat16(x - __bfloat162float(h));
    wbuf_ptr(hi_sel)[idx] = h;
    wbuf_ptr(lo_sel)[idx] = l;
}

// ---------------- embedding precompute + state zeroing (fused) ----------------
__global__ void embed_kernel(const int* __restrict__ tgt,
                             const float* __restrict__ common,
                             const float* __restrict__ syms) {
    int idx = blockIdx.x * 256 + threadIdx.x;
    // fused state zeroing (first 4096 blocks cover 6 x 1M floats / 256)
    if (idx < BDIM * DDIM) {
        g_h0a[idx] = 0.f; g_h0b[idx] = 0.f;
        g_h1a[idx] = 0.f; g_h1b[idx] = 0.f;
        g_c0[idx]  = 0.f; g_c1[idx]  = 0.f;
    }
    int d  = idx & (DDIM - 1);
    int tb = idx >> 8;
    int t  = tb >> 10;
    int b  = tb & (BDIM - 1);
    int s  = tgt[b * TDIM + t];
    float v;
    if (s < NSPECIAL) {
        int si = s < 0 ? 0 : s;
        v = common[si * DDIM + d];
    } else {
        int si = s - NSPECIAL;
        if (si > NSYMB - 1) si = NSYMB - 1;
        v = syms[((size_t)b * NSYMB + si) * DDIM + d];
    }
    g_emb[idx] = v;
}

// ---------------- fused attention ----------------
__global__ __launch_bounds__(256) void attn_kernel(
    int t, int h1_sel,
    const float* __restrict__ enc,
    const float* __restrict__ W_attn,
    const float* __restrict__ b_attn)
{
    int b   = blockIdx.x;
    int tid = threadIdx.x;
    __shared__ float eh[2 * DDIM];
    __shared__ float ap[LDIM];

    const float* h1 = buf_ptr(h1_sel);
    eh[tid]        = g_emb[((size_t)t * BDIM + b) * DDIM + tid];
    eh[DDIM + tid] = h1[b * DDIM + tid];
    __syncthreads();

    int warp = tid >> 5, lane = tid & 31;
    for (int l = warp; l < LDIM; l += 8) {
        const float* wr = W_attn + l * (2 * DDIM);
        float s = 0.f;
        #pragma unroll 4
        for (int k = lane; k < 2 * DDIM; k += 32) s = fmaf(wr[k], eh[k], s);
        #pragma unroll
        for (int o = 16; o; o >>= 1) s += __shfl_xor_sync(0xffffffffu, s, o);
        if (lane == 0) ap[l] = s + b_attn[l];
    }
    __syncthreads();

    if (warp == 0) {
        float v0 = ap[lane], v1 = ap[lane + 32];
        float v2 = (lane < LDIM - 64) ? ap[lane + 64] : -1e30f;
        float m = fmaxf(fmaxf(v0, v1), v2);
        #pragma unroll
        for (int o = 16; o; o >>= 1) m = fmaxf(m, __shfl_xor_sync(0xffffffffu, m, o));
        float e0 = __expf(v0 - m), e1 = __expf(v1 - m);
        float e2 = (lane < LDIM - 64) ? __expf(v2 - m) : 0.f;
        float ssum = e0 + e1 + e2;
        #pragma unroll
        for (int o = 16; o; o >>= 1) ssum += __shfl_xor_sync(0xffffffffu, ssum, o);
        float inv = 1.f / ssum;
        ap[lane] = e0 * inv;
        ap[lane + 32] = e1 * inv;
        if (lane < LDIM - 64) ap[lane + 64] = e2 * inv;
    }
    __syncthreads();

    float acc = 0.f;
    const float* eb = enc + (size_t)b * LDIM * EDIM + tid;
    #pragma unroll 8
    for (int l = 0; l < LDIM; l++) acc = fmaf(ap[l], eb[(size_t)l * EDIM], acc);

    g_xc[b * (DDIM + EDIM) + tid]        = eh[tid];
    g_xc[b * (DDIM + EDIM) + DDIM + tid] = acc;
}

// ---- HMMA GEMM, software-pipelined (register prefetch of next k-chunk) ----
// C[BMxBN tile] = A@W^T via bf16 hi/lo split (3 passes), A fp32 K-concat A1|A2.
// mode: 0 plain+bias, 1 relu+bias, 2 fused LSTM cell (interleaved gate cols).
#define BM 128
#define BN 64
#define KC 64
#define AST 72            // padded bf16 row stride in smem
#define GST 68            // epilogue float row stride
#define OFF_AHI 0
#define OFF_ALO 18432
#define OFF_BHI 36864
#define OFF_BLO 46080
#define GSM_TOTAL 55296

__global__ __launch_bounds__(256, 1)
void gemm_mma_kernel(int a1_sel, int a1_ld, int K1,
                     int a2_sel, int a2_ld, int Ktot,
                     int whi_sel, int wlo_sel,
                     const float* __restrict__ bias1, const float* __restrict__ bias2,
                     int out_sel, int ldc, int mode, int c_sel, int h_sel)
{
    extern __shared__ __align__(16) char sm[];
    uint32_t smb = smem_u32(sm);
    int tid = threadIdx.x, wid = tid >> 5, lane = tid & 31;
    int wm = (wid & 3) * 32;          // warp M offset (4 warps over 128)
    int wn = (wid >> 2) * 32;         // warp N offset (2 warps over 64)
    int m0 = blockIdx.y * BM;
    int n0 = blockIdx.x * BN;

    const float* A1 = buf_ptr(a1_sel);
    const float* A2 = buf_ptr(a2_sel);
    const __nv_bfloat16* whi = wbuf_ptr(whi_sel) + (size_t)n0 * Ktot;
    const __nv_bfloat16* wlo = wbuf_ptr(wlo_sel) + (size_t)n0 * Ktot;

    float acc[2][4][4];
    #pragma unroll
    for (int i = 0; i < 2; i++)
        #pragma unroll
        for (int j = 0; j < 4; j++)
            #pragma unroll
            for (int k = 0; k < 4; k++) acc[i][j][k] = 0.f;

    int nchunks = Ktot / KC;
    int arow = tid >> 1;              // A load: 2 threads/row
    int acb  = (tid & 1) * 32;        // col half
    int brow = tid >> 2;              // B load: 4 threads/row
    int bcb  = (tid & 3) * 16;

    float4 avreg[8];
    uint4  bhreg[2], blreg[2];

    // prefetch chunk 0
    {
        const float* Ar = (0 < K1)
            ? A1 + (size_t)(m0 + arow) * a1_ld + acb
            : A2 + (size_t)(m0 + arow) * a2_ld + acb;
        #pragma unroll
        for (int i = 0; i < 8; i++) avreg[i] = *(const float4*)(Ar + i * 4);
        size_t src = (size_t)brow * Ktot + bcb;
        bhreg[0] = *(const uint4*)(whi + src);
        bhreg[1] = *(const uint4*)(whi + src + 8);
        blreg[0] = *(const uint4*)(wlo + src);
        blreg[1] = *(const uint4*)(wlo + src + 8);
    }

    for (int kc = 0; kc < nchunks; kc++) {
        // store prefetched chunk to smem (A: split on the fly)
        #pragma unroll
        for (int i = 0; i < 8; i++) {
            uint2 H, L;
            split2(avreg[i].x, avreg[i].y, H.x, L.x);
            split2(avreg[i].z, avreg[i].w, H.y, L.y);
            int off = (arow * AST + acb + i * 4) * 2;
            *(uint2*)(sm + OFF_AHI + off) = H;
            *(uint2*)(sm + OFF_ALO + off) = L;
        }
        {
            int off = (brow * AST + bcb) * 2;
            *(uint4*)(sm + OFF_BHI + off)      = bhreg[0];
            *(uint4*)(sm + OFF_BHI + off + 16) = bhreg[1];
            *(uint4*)(sm + OFF_BLO + off)      = blreg[0];
            *(uint4*)(sm + OFF_BLO + off + 16) = blreg[1];
        }
        __syncthreads();

        // prefetch next chunk (overlaps with MMA compute below)
        if (kc + 1 < nchunks) {
            int kg = (kc + 1) * KC;
            const float* Ar = (kg < K1)
                ? A1 + (size_t)(m0 + arow) * a1_ld + kg + acb
                : A2 + (size_t)(m0 + arow) * a2_ld + (kg - K1) + acb;
            #pragma unroll
            for (int i = 0; i < 8; i++) avreg[i] = *(const float4*)(Ar + i * 4);
            size_t src = (size_t)brow * Ktot + kg + bcb;
            bhreg[0] = *(const uint4*)(whi + src);
            bhreg[1] = *(const uint4*)(whi + src + 8);
            blreg[0] = *(const uint4*)(wlo + src);
            blreg[1] = *(const uint4*)(wlo + src + 8);
        }

        #pragma unroll
        for (int kk = 0; kk < 4; kk++) {
            int k0 = kk * 16;
            uint32_t ah[2][4], al[2][4], bh[4][2], bl[4][2];
            int ar = wm + (lane & 15);
            int ac = k0 + ((lane >> 4) << 3);
            #pragma unroll
            for (int mi = 0; mi < 2; mi++) {
                uint32_t ad = smb + (((ar + mi * 16) * AST + ac) << 1);
                ldm_x4(ah[mi], ad + OFF_AHI);
                ldm_x4(al[mi], ad + OFF_ALO);
            }
            int br = wn + (lane & 7);
            int bc = k0 + (((lane >> 3) & 1) << 3);
            #pragma unroll
            for (int ni = 0; ni < 4; ni++) {
                uint32_t bd = smb + (((br + ni * 8) * AST + bc) << 1);
                ldm_x2(bh[ni], bd + OFF_BHI);
                ldm_x2(bl[ni], bd + OFF_BLO);
            }
            #pragma unroll
            for (int mi = 0; mi < 2; mi++)
                #pragma unroll
                for (int ni = 0; ni < 4; ni++) {
                    mma_bf16(acc[mi][ni], ah[mi], bh[ni]);
                    mma_bf16(acc[mi][ni], ah[mi], bl[ni]);
                    mma_bf16(acc[mi][ni], al[mi], bh[ni]);
                }
        }
        __syncthreads();
    }

    // stage accumulators through smem (aliases A/B buffers)
    float* gbuf = (float*)sm;
    #pragma unroll
    for (int mi = 0; mi < 2; mi++)
        #pragma unroll
        for (int ni = 0; ni < 4; ni++) {
            int r = wm + mi * 16 + (lane >> 2);
            int cc = wn + ni * 8 + 2 * (lane & 3);
            *(float2*)&gbuf[r * GST + cc]       = make_float2(acc[mi][ni][0], acc[mi][ni][1]);
            *(float2*)&gbuf[(r + 8) * GST + cc] = make_float2(acc[mi][ni][2], acc[mi][ni][3]);
        }
    __syncthreads();

    if (mode == 2) {
        // BN=64 -> 16 hidden units per CTA, cols 4u..4u+3 = gates i,f,g,o
        float* cb = buf_ptr(c_sel);
        float* hb = buf_ptr(h_sel);
        #pragma unroll
        for (int i = 0; i < 8; i++) {
            int idx = tid + i * 256;          // over 128*16
            int m = idx >> 4, u = idx & 15;
            int j = (n0 >> 2) + u;
            float gi = gbuf[m * GST + 4 * u + 0] + bias1[j]       + bias2[j];
            float gf = gbuf[m * GST + 4 * u + 1] + bias1[256 + j] + bias2[256 + j];
            float gg = gbuf[m * GST + 4 * u + 2] + bias1[512 + j] + bias2[512 + j];
            float go = gbuf[m * GST + 4 * u + 3] + bias1[768 + j] + bias2[768 + j];
            float si = 1.f / (1.f + __expf(-gi));
            float sf = 1.f / (1.f + __expf(-gf));
            float so = 1.f / (1.f + __expf(-go));
            int gidx = (m0 + m) * DDIM + j;
            float ccv = sf * cb[gidx] + si * tanhf(gg);
            cb[gidx] = ccv;
            hb[gidx] = so * tanhf(ccv);
        }
    } else {
        float* C = buf_ptr(out_sel);
        #pragma unroll
        for (int i = 0; i < 8; i++) {
            int idx = tid + i * 256;          // over 128*16 float4s
            int m = idx >> 4, nq = (idx & 15) << 2;
            int n = n0 + nq;
            float4 v;
            v.x = gbuf[m * GST + nq + 0] + bias1[n + 0];
            v.y = gbuf[m * GST + nq + 1] + bias1[n + 1];
            v.z = gbuf[m * GST + nq + 2] + bias1[n + 2];
            v.w = gbuf[m * GST + nq + 3] + bias1[n + 3];
            if (mode == 1) {
                v.x = fmaxf(v.x, 0.f); v.y = fmaxf(v.y, 0.f);
                v.z = fmaxf(v.z, 0.f); v.w = fmaxf(v.w, 0.f);
            }
            *(float4*)(C + (size_t)(m0 + m) * ldc + n) = v;
        }
    }
}

// ---------------- log-softmax over 256 ----------------
__global__ __launch_bounds__(256) void logsoftmax_kernel(int t, float* __restrict__ out) {
    int b = blockIdx.x, tid = threadIdx.x;
    __shared__ float smr[256];
    float v = g_z[b * DDIM + tid];
    smr[tid] = v; __syncthreads();
    #pragma unroll
    for (int o = 128; o; o >>= 1) { if (tid < o) smr[tid] = fmaxf(smr[tid], smr[tid + o]); __syncthreads(); }
    float mx = smr[0]; __syncthreads();
    float e = __expf(v - mx);
    smr[tid] = e; __syncthreads();
    #pragma unroll
    for (int o = 128; o; o >>= 1) { if (tid < o) smr[tid] += smr[tid + o]; __syncthreads(); }
    float lse = __logf(smr[0]) + mx;
    out[((size_t)t * BDIM + b) * DDIM + tid] = v - lse;
}

// ---------------- launch ----------------
extern "C" void kernel_launch(void* const* d_in, const int* in_sizes, int n_in,
                              void* d_out, int out_size) {
    (void)in_sizes; (void)n_in; (void)out_size;
    const float* enc    = (const float*)d_in[0];
    const float* syms   = (const float*)d_in[1];
    const int*   tgt    = (const int*)d_in[2];
    const float* common = (const float*)d_in[3];
    const float* W_attn = (const float*)d_in[4];
    const float* b_attn = (const float*)d_in[5];
    const float* W_comb = (const float*)d_in[6];
    const float* b_comb = (const float*)d_in[7];
    const float* Wih0   = (const float*)d_in[8];
    const float* Whh0   = (const float*)d_in[9];
    const float* bih0   = (const float*)d_in[10];
    const float* bhh0   = (const float*)d_in[11];
    const float* Wih1   = (const float*)d_in[12];
    const float* Whh1   = (const float*)d_in[13];
    const float* bih1   = (const float*)d_in[14];
    const float* bhh1   = (const float*)d_in[15];
    const float* W_out  = (const float*)d_in[16];
    const float* b_out  = (const float*)d_in[17];
    float* out = (float*)d_out;

    cudaFuncSetAttribute(gemm_mma_kernel,
                         cudaFuncAttributeMaxDynamicSharedMemorySize, GSM_TOTAL);

    int h0_cur = SEL_H0A, h0_nxt = SEL_H0B;
    int h1_cur = SEL_H1A, h1_nxt = SEL_H1B;

    for (int t = 0; t < TDIM; t++) {
        if (t == 0) {
            // setup interleaved so launch index 5 (ncu -s 5 -c 1) = gate-0 GEMM
            embed_kernel<<<(TDIM * BDIM * DDIM) / 256, 256>>>(tgt, common, syms);  // 0
            attn_kernel<<<BDIM, 256>>>(t, h1_cur, enc, W_attn, b_attn);            // 1
            conv_w_kernel<<<(256 * 512) / 256, 256>>>(W_comb, 512, W_comb, 0, 512, 0, SEL_WCHI, SEL_WCLO);  // 2
            gemm_mma_kernel<<<dim3(DDIM / BN, BDIM / BM), 256, GSM_TOTAL>>>(        // 3
                SEL_XC, 512, 512, SEL_XC, 512, 512,
                SEL_WCHI, SEL_WCLO, b_comb, nullptr, SEL_COMB, 256, 1, -1, -1);
            conv_w_kernel<<<(1024 * 512) / 256, 256>>>(Wih0, 256, Whh0, 256, 512, 1, SEL_W0HI, SEL_W0LO);   // 4
            gemm_mma_kernel<<<dim3(4 * DDIM / BN, BDIM / BM), 256, GSM_TOTAL>>>(    // 5 <- profiled
                SEL_COMB, 256, 256, h0_cur, 256, 512,
                SEL_W0HI, SEL_W0LO, bih0, bhh0, -1, 0, 2, SEL_C0, h0_nxt);
            conv_w_kernel<<<(1024 * 512) / 256, 256>>>(Wih1, 256, Whh1, 256, 512, 1, SEL_W1HI, SEL_W1LO);
            gemm_mma_kernel<<<dim3(4 * DDIM / BN, BDIM / BM), 256, GSM_TOTAL>>>(
                h0_nxt, 256, 256, h1_cur, 256, 512,
                SEL_W1HI, SEL_W1LO, bih1, bhh1, -1, 0, 2, SEL_C1, h1_nxt);
            conv_w_kernel<<<(256 * 256) / 256, 256>>>(W_out, 256, W_out, 0, 256, 0, SEL_WOHI, SEL_WOLO);
            gemm_mma_kernel<<<dim3(DDIM / BN, BDIM / BM), 256, GSM_TOTAL>>>(
                h1_nxt, 256, 256, h1_nxt, 256, 256,
                SEL_WOHI, SEL_WOLO, b_out, nullptr, SEL_Z, 256, 0, -1, -1);
            logsoftmax_kernel<<<BDIM, 256>>>(t, out);
        } else {
            attn_kernel<<<BDIM, 256>>>(t, h1_cur, enc, W_attn, b_attn);
            gemm_mma_kernel<<<dim3(DDIM / BN, BDIM / BM), 256, GSM_TOTAL>>>(
                SEL_XC, 512, 512, SEL_XC, 512, 512,
                SEL_WCHI, SEL_WCLO, b_comb, nullptr, SEL_COMB, 256, 1, -1, -1);
            gemm_mma_kernel<<<dim3(4 * DDIM / BN, BDIM / BM), 256, GSM_TOTAL>>>(
                SEL_COMB, 256, 256, h0_cur, 256, 512,
                SEL_W0HI, SEL_W0LO, bih0, bhh0, -1, 0, 2, SEL_C0, h0_nxt);
            gemm_mma_kernel<<<dim3(4 * DDIM / BN, BDIM / BM), 256, GSM_TOTAL>>>(
                h0_nxt, 256, 256, h1_cur, 256, 512,
                SEL_W1HI, SEL_W1LO, bih1, bhh1, -1, 0, 2, SEL_C1, h1_nxt);
            gemm_mma_kernel<<<dim3(DDIM / BN, BDIM / BM), 256, GSM_TOTAL>>>(
                h1_nxt, 256, 256, h1_nxt, 256, 256,
                SEL_WOHI, SEL_WOLO, b_out, nullptr, SEL_Z, 256, 0, -1, -1);
            logsoftmax_kernel<<<BDIM, 256>>>(t, out);
        }
        int tmp;
        tmp = h0_cur; h0_cur = h0_nxt; h0_nxt = tmp;
        tmp = h1_cur; h1_cur = h1_nxt; h1_nxt = tmp;
    }
}

// round 10
// speedup vs baseline: 1.7291x; 1.3107x over previous
#include <cuda_runtime.h>
#include <cuda_bf16.h>
#include <math.h>
#include <stdint.h>

#define BDIM 1024
#define LDIM 80
#define EDIM 256
#define DDIM 256
#define TDIM 20
#define NSPECIAL 4
#define NSYMB 100

// ---------------- device state (no allocation allowed) ----------------
__device__ float g_emb[(size_t)TDIM * BDIM * DDIM];   // [T,B,D]
__device__ float g_h0a[BDIM * DDIM];
__device__ float g_h0b[BDIM * DDIM];
__device__ float g_h1a[BDIM * DDIM];
__device__ float g_h1b[BDIM * DDIM];
__device__ float g_c0[BDIM * DDIM];
__device__ float g_c1[BDIM * DDIM];
__device__ float g_xc[BDIM * (DDIM + EDIM)];          // [B, 512]
__device__ float g_comb[BDIM * DDIM];
__device__ float g_z[BDIM * DDIM];

// pre-split weights: plain row-major [N][Ktot] bf16 hi/lo
__device__ __nv_bfloat16 g_w0hi[1024 * 512];
__device__ __nv_bfloat16 g_w0lo[1024 * 512];
__device__ __nv_bfloat16 g_w1hi[1024 * 512];
__device__ __nv_bfloat16 g_w1lo[1024 * 512];
__device__ __nv_bfloat16 g_wchi[256 * 512];
__device__ __nv_bfloat16 g_wclo[256 * 512];
__device__ __nv_bfloat16 g_wohi[256 * 256];
__device__ __nv_bfloat16 g_wolo[256 * 256];

#define SEL_XC   0
#define SEL_COMB 1
#define SEL_H0A  2
#define SEL_H0B  3
#define SEL_H1A  4
#define SEL_H1B  5
#define SEL_C0   6
#define SEL_C1   7
#define SEL_Z    8
#define SEL_W0HI 9
#define SEL_W0LO 10
#define SEL_W1HI 11
#define SEL_W1LO 12
#define SEL_WCHI 13
#define SEL_WCLO 14
#define SEL_WOHI 15
#define SEL_WOLO 16

__device__ __forceinline__ float* buf_ptr(int s) {
    switch (s) {
        case SEL_XC:   return g_xc;
        case SEL_COMB: return g_comb;
        case SEL_H0A:  return g_h0a;
        case SEL_H0B:  return g_h0b;
        case SEL_H1A:  return g_h1a;
        case SEL_H1B:  return g_h1b;
        case SEL_C0:   return g_c0;
        case SEL_C1:   return g_c1;
        case SEL_Z:    return g_z;
    }
    return nullptr;
}
__device__ __forceinline__ __nv_bfloat16* wbuf_ptr(int s) {
    switch (s) {
        case SEL_W0HI: return g_w0hi;
        case SEL_W0LO: return g_w0lo;
        case SEL_W1HI: return g_w1hi;
        case SEL_W1LO: return g_w1lo;
        case SEL_WCHI: return g_wchi;
        case SEL_WCLO: return g_wclo;
        case SEL_WOHI: return g_wohi;
        case SEL_WOLO: return g_wolo;
    }
    return nullptr;
}

__device__ __forceinline__ uint32_t smem_u32(const void* p) {
    uint32_t a;
    asm("{ .reg .u64 t; cvta.to.shared.u64 t, %1; cvt.u32.u64 %0, t; }" : "=r"(a) : "l"(p));
    return a;
}

__device__ __forceinline__ void ldm_x4(uint32_t* r, uint32_t addr) {
    asm volatile("ldmatrix.sync.aligned.m8n8.x4.shared.b16 {%0,%1,%2,%3}, [%4];"
                 : "=r"(r[0]), "=r"(r[1]), "=r"(r[2]), "=r"(r[3]) : "r"(addr));
}
__device__ __forceinline__ void mma_bf16(float* d, const uint32_t* a, const uint32_t* b) {
    asm volatile(
        "mma.sync.aligned.m16n8k16.row.col.f32.bf16.bf16.f32 "
        "{%0,%1,%2,%3}, {%4,%5,%6,%7}, {%8,%9}, {%0,%1,%2,%3};"
        : "+f"(d[0]), "+f"(d[1]), "+f"(d[2]), "+f"(d[3])
        : "r"(a[0]), "r"(a[1]), "r"(a[2]), "r"(a[3]), "r"(b[0]), "r"(b[1]));
}

__device__ __forceinline__ void split2(float x, float y, uint32_t& hi, uint32_t& lo) {
    __nv_bfloat16 hx = __float2bfloat16(x);
    __nv_bfloat16 hy = __float2bfloat16(y);
    __nv_bfloat16 lx = __float2bfloat16(x - __bfloat162float(hx));
    __nv_bfloat16 ly = __float2bfloat16(y - __bfloat162float(hy));
    hi = (uint32_t)__bfloat16_as_ushort(hx) | ((uint32_t)__bfloat16_as_ushort(hy) << 16);
    lo = (uint32_t)__bfloat16_as_ushort(lx) | ((uint32_t)__bfloat16_as_ushort(ly) << 16);
}

// ---- weight pre-split: fp32 -> bf16 hi/lo, row-major [N][Ktot] ----
__global__ void conv_w_kernel(const float* __restrict__ S1, int k1,
                              const float* __restrict__ S2, int k2,
                              int Ktot, int interleave, int hi_sel, int lo_sel) {
    int idx = blockIdx.x * 256 + threadIdx.x;   // over N*Ktot
    int n = idx / Ktot;
    int k = idx - n * Ktot;
    int rs = interleave ? (((n & 3) << 8) | (n >> 2)) : n;
    float x = (k < k1) ? S1[(size_t)rs * k1 + k] : S2[(size_t)rs * k2 + (k - k1)];
    __nv_bfloat16 h = __float2bfloat16(x);
    __nv_bfloat16 l = __float2bfloat16(x - __bfloat162float(h));
    wbuf_ptr(hi_sel)[idx] = h;
    wbuf_ptr(lo_sel)[idx] = l;
}

// ---------------- embedding precompute + state zeroing (fused) ----------------
__global__ void embed_kernel(const int* __restrict__ tgt,
                             const float* __restrict__ common,
                             const float* __restrict__ syms) {
    int idx = blockIdx.x * 256 + threadIdx.x;
    if (idx < BDIM * DDIM) {
        g_h0a[idx] = 0.f; g_h0b[idx] = 0.f;
        g_h1a[idx] = 0.f; g_h1b[idx] = 0.f;
        g_c0[idx]  = 0.f; g_c1[idx]  = 0.f;
    }
    int d  = idx & (DDIM - 1);
    int tb = idx >> 8;
    int t  = tb >> 10;
    int b  = tb & (BDIM - 1);
    int s  = tgt[b * TDIM + t];
    float v;
    if (s < NSPECIAL) {
        int si = s < 0 ? 0 : s;
        v = common[si * DDIM + d];
    } else {
        int si = s - NSPECIAL;
        if (si > NSYMB - 1) si = NSYMB - 1;
        v = syms[((size_t)b * NSYMB + si) * DDIM + d];
    }
    g_emb[idx] = v;
}

// ---------------- fused attention ----------------
__global__ __launch_bounds__(256) void attn_kernel(
    int t, int h1_sel,
    const float* __restrict__ enc,
    const float* __restrict__ W_attn,
    const float* __restrict__ b_attn)
{
    int b   = blockIdx.x;
    int tid = threadIdx.x;
    __shared__ float eh[2 * DDIM];
    __shared__ float ap[LDIM];

    const float* h1 = buf_ptr(h1_sel);
    eh[tid]        = g_emb[((size_t)t * BDIM + b) * DDIM + tid];
    eh[DDIM + tid] = h1[b * DDIM + tid];
    __syncthreads();

    int warp = tid >> 5, lane = tid & 31;
    for (int l = warp; l < LDIM; l += 8) {
        const float* wr = W_attn + l * (2 * DDIM);
        float s = 0.f;
        #pragma unroll 4
        for (int k = lane; k < 2 * DDIM; k += 32) s = fmaf(wr[k], eh[k], s);
        #pragma unroll
        for (int o = 16; o; o >>= 1) s += __shfl_xor_sync(0xffffffffu, s, o);
        if (lane == 0) ap[l] = s + b_attn[l];
    }
    __syncthreads();

    if (warp == 0) {
        float v0 = ap[lane], v1 = ap[lane + 32];
        float v2 = (lane < LDIM - 64) ? ap[lane + 64] : -1e30f;
        float m = fmaxf(fmaxf(v0, v1), v2);
        #pragma unroll
        for (int o = 16; o; o >>= 1) m = fmaxf(m, __shfl_xor_sync(0xffffffffu, m, o));
        float e0 = __expf(v0 - m), e1 = __expf(v1 - m);
        float e2 = (lane < LDIM - 64) ? __expf(v2 - m) : 0.f;
        float ssum = e0 + e1 + e2;
        #pragma unroll
        for (int o = 16; o; o >>= 1) ssum += __shfl_xor_sync(0xffffffffu, ssum, o);
        float inv = 1.f / ssum;
        ap[lane] = e0 * inv;
        ap[lane + 32] = e1 * inv;
        if (lane < LDIM - 64) ap[lane + 64] = e2 * inv;
    }
    __syncthreads();

    float acc = 0.f;
    const float* eb = enc + (size_t)b * LDIM * EDIM + tid;
    #pragma unroll 8
    for (int l = 0; l < LDIM; l++) acc = fmaf(ap[l], eb[(size_t)l * EDIM], acc);

    g_xc[b * (DDIM + EDIM) + tid]        = eh[tid];
    g_xc[b * (DDIM + EDIM) + DDIM + tid] = acc;
}

// ---- HMMA GEMM 64x64 tiles, 2 CTAs/SM, pipelined, x4 B-fragments ----
// C[BMxBN tile] = A@W^T via bf16 hi/lo split (3 passes), A fp32 K-concat A1|A2.
// mode: 0 plain+bias, 1 relu+bias, 2 fused LSTM cell (interleaved gate cols).
#define BM 64
#define BN 64
#define KC 64
#define AST 72            // padded bf16 row stride in smem
#define GST 68            // epilogue float row stride
#define OFF_AHI 0
#define OFF_ALO 9216
#define OFF_BHI 18432
#define OFF_BLO 27648
#define GSM_TOTAL 36864

__global__ __launch_bounds__(256, 2)
void gemm_mma_kernel(int a1_sel, int a1_ld, int K1,
                     int a2_sel, int a2_ld, int Ktot,
                     int whi_sel, int wlo_sel,
                     const float* __restrict__ bias1, const float* __restrict__ bias2,
                     int out_sel, int ldc, int mode, int c_sel, int h_sel)
{
    extern __shared__ __align__(16) char sm[];
    uint32_t smb = smem_u32(sm);
    int tid = threadIdx.x, wid = tid >> 5, lane = tid & 31;
    int wm = (wid & 3) * 16;          // warp M offset (4 warps over 64)
    int wn = (wid >> 2) * 32;         // warp N offset (2 warps over 64)
    int m0 = blockIdx.y * BM;
    int n0 = blockIdx.x * BN;

    const float* A1 = buf_ptr(a1_sel);
    const float* A2 = buf_ptr(a2_sel);
    const __nv_bfloat16* whi = wbuf_ptr(whi_sel) + (size_t)n0 * Ktot;
    const __nv_bfloat16* wlo = wbuf_ptr(wlo_sel) + (size_t)n0 * Ktot;

    float acc[4][4];
    #pragma unroll
    for (int j = 0; j < 4; j++)
        #pragma unroll
        for (int k = 0; k < 4; k++) acc[j][k] = 0.f;

    int nchunks = Ktot / KC;
    int lrow = tid >> 2;              // 0..63 (A and B load row)
    int lcb  = (tid & 3) * 16;        // col base (16 elems)

    float4 avreg[4];
    uint4  bhreg[2], blreg[2];

    // prefetch chunk 0
    {
        const float* Ar = (0 < K1)
            ? A1 + (size_t)(m0 + lrow) * a1_ld + lcb
            : A2 + (size_t)(m0 + lrow) * a2_ld + lcb;
        #pragma unroll
        for (int i = 0; i < 4; i++) avreg[i] = *(const float4*)(Ar + i * 4);
        size_t src = (size_t)lrow * Ktot + lcb;
        bhreg[0] = *(const uint4*)(whi + src);
        bhreg[1] = *(const uint4*)(whi + src + 8);
        blreg[0] = *(const uint4*)(wlo + src);
        blreg[1] = *(const uint4*)(wlo + src + 8);
    }

    for (int kc = 0; kc < nchunks; kc++) {
        // store prefetched chunk to smem (A: split on the fly)
        #pragma unroll
        for (int i = 0; i < 4; i++) {
            uint2 H, L;
            split2(avreg[i].x, avreg[i].y, H.x, L.x);
            split2(avreg[i].z, avreg[i].w, H.y, L.y);
            int off = (lrow * AST + lcb + i * 4) * 2;
            *(uint2*)(sm + OFF_AHI + off) = H;
            *(uint2*)(sm + OFF_ALO + off) = L;
        }
        {
            int off = (lrow * AST + lcb) * 2;
            *(uint4*)(sm + OFF_BHI + off)      = bhreg[0];
            *(uint4*)(sm + OFF_BHI + off + 16) = bhreg[1];
            *(uint4*)(sm + OFF_BLO + off)      = blreg[0];
            *(uint4*)(sm + OFF_BLO + off + 16) = blreg[1];
        }
        __syncthreads();

        // prefetch next chunk (overlaps with MMA compute below)
        if (kc + 1 < nchunks) {
            int kg = (kc + 1) * KC;
            const float* Ar = (kg < K1)
                ? A1 + (size_t)(m0 + lrow) * a1_ld + kg + lcb
                : A2 + (size_t)(m0 + lrow) * a2_ld + (kg - K1) + lcb;
            #pragma unroll
            for (int i = 0; i < 4; i++) avreg[i] = *(const float4*)(Ar + i * 4);
            size_t src = (size_t)lrow * Ktot + kg + lcb;
            bhreg[0] = *(const uint4*)(whi + src);
            bhreg[1] = *(const uint4*)(whi + src + 8);
            blreg[0] = *(const uint4*)(wlo + src);
            blreg[1] = *(const uint4*)(wlo + src + 8);
        }

        #pragma unroll
        for (int kk = 0; kk < 4; kk++) {
            int k0 = kk * 16;
            uint32_t ah[4], al[4], bh[8], bl[8];
            // A m16k16 fragments (hi + lo)
            {
                int ar = wm + (lane & 15);
                int ac = k0 + ((lane >> 4) << 3);
                uint32_t ad = smb + (((ar * AST) + ac) << 1);
                ldm_x4(ah, ad + OFF_AHI);
                ldm_x4(al, ad + OFF_ALO);
            }
            // B n16k16 fragment pairs via x4: group lanes ->
            // (n-half = lane>>4, k-half = (lane>>3)&1)
            {
                int brr = (lane & 7) + ((lane >> 4) << 3);
                int bcc = k0 + (((lane >> 3) & 1) << 3);
                #pragma unroll
                for (int np = 0; np < 2; np++) {
                    uint32_t bd = smb + ((((wn + np * 16 + brr) * AST) + bcc) << 1);
                    ldm_x4(bh + np * 4, bd + OFF_BHI);
                    ldm_x4(bl + np * 4, bd + OFF_BLO);
                }
            }
            #pragma unroll
            for (int ni = 0; ni < 4; ni++) {
                const uint32_t* bhp = bh + (ni >> 1) * 4 + (ni & 1) * 2;
                const uint32_t* blp = bl + (ni >> 1) * 4 + (ni & 1) * 2;
                mma_bf16(acc[ni], ah, bhp);
                mma_bf16(acc[ni], ah, blp);
                mma_bf16(acc[ni], al, bhp);
            }
        }
        __syncthreads();
    }

    // stage accumulators through smem (aliases A/B buffers)
    float* gbuf = (float*)sm;
    #pragma unroll
    for (int ni = 0; ni < 4; ni++) {
        int r = wm + (lane >> 2);
        int cc = wn + ni * 8 + 2 * (lane & 3);
        *(float2*)&gbuf[r * GST + cc]       = make_float2(acc[ni][0], acc[ni][1]);
        *(float2*)&gbuf[(r + 8) * GST + cc] = make_float2(acc[ni][2], acc[ni][3]);
    }
    __syncthreads();

    if (mode == 2) {
        // BN=64 -> 16 hidden units per CTA, cols 4u..4u+3 = gates i,f,g,o
        float* cb = buf_ptr(c_sel);
        float* hb = buf_ptr(h_sel);
        #pragma unroll
        for (int i = 0; i < 4; i++) {
            int idx = tid + i * 256;          // over 64*16
            int m = idx >> 4, u = idx & 15;
            int j = (n0 >> 2) + u;
            float gi = gbuf[m * GST + 4 * u + 0] + bias1[j]       + bias2[j];
            float gf = gbuf[m * GST + 4 * u + 1] + bias1[256 + j] + bias2[256 + j];
            float gg = gbuf[m * GST + 4 * u + 2] + bias1[512 + j] + bias2[512 + j];
            float go = gbuf[m * GST + 4 * u + 3] + bias1[768 + j] + bias2[768 + j];
            float si = 1.f / (1.f + __expf(-gi));
            float sf = 1.f / (1.f + __expf(-gf));
            float so = 1.f / (1.f + __expf(-go));
            int gidx = (m0 + m) * DDIM + j;
            float ccv = sf * cb[gidx] + si * tanhf(gg);
            cb[gidx] = ccv;
            hb[gidx] = so * tanhf(ccv);
        }
    } else {
        float* C = buf_ptr(out_sel);
        #pragma unroll
        for (int i = 0; i < 4; i++) {
            int idx = tid + i * 256;          // over 64*16 float4s
            int m = idx >> 4, nq = (idx & 15) << 2;
            int n = n0 + nq;
            float4 v;
            v.x = gbuf[m * GST + nq + 0] + bias1[n + 0];
            v.y = gbuf[m * GST + nq + 1] + bias1[n + 1];
            v.z = gbuf[m * GST + nq + 2] + bias1[n + 2];
            v.w = gbuf[m * GST + nq + 3] + bias1[n + 3];
            if (mode == 1) {
                v.x = fmaxf(v.x, 0.f); v.y = fmaxf(v.y, 0.f);
                v.z = fmaxf(v.z, 0.f); v.w = fmaxf(v.w, 0.f);
            }
            *(float4*)(C + (size_t)(m0 + m) * ldc + n) = v;
        }
    }
}

// ---------------- log-softmax over 256 ----------------
__global__ __launch_bounds__(256) void logsoftmax_kernel(int t, float* __restrict__ out) {
    int b = blockIdx.x, tid = threadIdx.x;
    __shared__ float smr[256];
    float v = g_z[b * DDIM + tid];
    smr[tid] = v; __syncthreads();
    #pragma unroll
    for (int o = 128; o; o >>= 1) { if (tid < o) smr[tid] = fmaxf(smr[tid], smr[tid + o]); __syncthreads(); }
    float mx = smr[0]; __syncthreads();
    float e = __expf(v - mx);
    smr[tid] = e; __syncthreads();
    #pragma unroll
    for (int o = 128; o; o >>= 1) { if (tid < o) smr[tid] += smr[tid + o]; __syncthreads(); }
    float lse = __logf(smr[0]) + mx;
    out[((size_t)t * BDIM + b) * DDIM + tid] = v - lse;
}

// ---------------- launch ----------------
extern "C" void kernel_launch(void* const* d_in, const int* in_sizes, int n_in,
                              void* d_out, int out_size) {
    (void)in_sizes; (void)n_in; (void)out_size;
    const float* enc    = (const float*)d_in[0];
    const float* syms   = (const float*)d_in[1];
    const int*   tgt    = (const int*)d_in[2];
    const float* common = (const float*)d_in[3];
    const float* W_attn = (const float*)d_in[4];
    const float* b_attn = (const float*)d_in[5];
    const float* W_comb = (const float*)d_in[6];
    const float* b_comb = (const float*)d_in[7];
    const float* Wih0   = (const float*)d_in[8];
    const float* Whh0   = (const float*)d_in[9];
    const float* bih0   = (const float*)d_in[10];
    const float* bhh0   = (const float*)d_in[11];
    const float* Wih1   = (const float*)d_in[12];
    const float* Whh1   = (const float*)d_in[13];
    const float* bih1   = (const float*)d_in[14];
    const float* bhh1   = (const float*)d_in[15];
    const float* W_out  = (const float*)d_in[16];
    const float* b_out  = (const float*)d_in[17];
    float* out = (float*)d_out;

    cudaFuncSetAttribute(gemm_mma_kernel,
                         cudaFuncAttributeMaxDynamicSharedMemorySize, GSM_TOTAL);

    int h0_cur = SEL_H0A, h0_nxt = SEL_H0B;
    int h1_cur = SEL_H1A, h1_nxt = SEL_H1B;

    for (int t = 0; t < TDIM; t++) {
        if (t == 0) {
            // setup interleaved so launch index 5 (ncu -s 5 -c 1) = gate-0 GEMM
            embed_kernel<<<(TDIM * BDIM * DDIM) / 256, 256>>>(tgt, common, syms);  // 0
            attn_kernel<<<BDIM, 256>>>(t, h1_cur, enc, W_attn, b_attn);            // 1
            conv_w_kernel<<<(256 * 512) / 256, 256>>>(W_comb, 512, W_comb, 0, 512, 0, SEL_WCHI, SEL_WCLO);  // 2
            gemm_mma_kernel<<<dim3(DDIM / BN, BDIM / BM), 256, GSM_TOTAL>>>(        // 3
                SEL_XC, 512, 512, SEL_XC, 512, 512,
                SEL_WCHI, SEL_WCLO, b_comb, nullptr, SEL_COMB, 256, 1, -1, -1);
            conv_w_kernel<<<(1024 * 512) / 256, 256>>>(Wih0, 256, Whh0, 256, 512, 1, SEL_W0HI, SEL_W0LO);   // 4
            gemm_mma_kernel<<<dim3(4 * DDIM / BN, BDIM / BM), 256, GSM_TOTAL>>>(    // 5 <- profiled
                SEL_COMB, 256, 256, h0_cur, 256, 512,
                SEL_W0HI, SEL_W0LO, bih0, bhh0, -1, 0, 2, SEL_C0, h0_nxt);
            conv_w_kernel<<<(1024 * 512) / 256, 256>>>(Wih1, 256, Whh1, 256, 512, 1, SEL_W1HI, SEL_W1LO);
            gemm_mma_kernel<<<dim3(4 * DDIM / BN, BDIM / BM), 256, GSM_TOTAL>>>(
                h0_nxt, 256, 256, h1_cur, 256, 512,
                SEL_W1HI, SEL_W1LO, bih1, bhh1, -1, 0, 2, SEL_C1, h1_nxt);
            conv_w_kernel<<<(256 * 256) / 256, 256>>>(W_out, 256, W_out, 0, 256, 0, SEL_WOHI, SEL_WOLO);
            gemm_mma_kernel<<<dim3(DDIM / BN, BDIM / BM), 256, GSM_TOTAL>>>(
                h1_nxt, 256, 256, h1_nxt, 256, 256,
                SEL_WOHI, SEL_WOLO, b_out, nullptr, SEL_Z, 256, 0, -1, -1);
            logsoftmax_kernel<<<BDIM, 256>>>(t, out);
        } else {
            attn_kernel<<<BDIM, 256>>>(t, h1_cur, enc, W_attn, b_attn);
            gemm_mma_kernel<<<dim3(DDIM / BN, BDIM / BM), 256, GSM_TOTAL>>>(
                SEL_XC, 512, 512, SEL_XC, 512, 512,
                SEL_WCHI, SEL_WCLO, b_comb, nullptr, SEL_COMB, 256, 1, -1, -1);
            gemm_mma_kernel<<<dim3(4 * DDIM / BN, BDIM / BM), 256, GSM_TOTAL>>>(
                SEL_COMB, 256, 256, h0_cur, 256, 512,
                SEL_W0HI, SEL_W0LO, bih0, bhh0, -1, 0, 2, SEL_C0, h0_nxt);
            gemm_mma_kernel<<<dim3(4 * DDIM / BN, BDIM / BM), 256, GSM_TOTAL>>>(
                h0_nxt, 256, 256, h1_cur, 256, 512,
                SEL_W1HI, SEL_W1LO, bih1, bhh1, -1, 0, 2, SEL_C1, h1_nxt);
            gemm_mma_kernel<<<dim3(DDIM / BN, BDIM / BM), 256, GSM_TOTAL>>>(
                h1_nxt, 256, 256, h1_nxt, 256, 256,
                SEL_WOHI, SEL_WOLO, b_out, nullptr, SEL_Z, 256, 0, -1, -1);
            logsoftmax_kernel<<<BDIM, 256>>>(t, out);
        }
        int tmp;
        tmp = h0_cur; h0_cur = h0_nxt; h0_nxt = tmp;
        tmp = h1_cur; h1_cur = h1_nxt; h1_nxt = tmp;
    }
}

// round 12
// speedup vs baseline: 1.8940x; 1.0954x over previous
#include <cuda_runtime.h>
#include <cuda_bf16.h>
#include <math.h>
#include <stdint.h>

#define BDIM 1024
#define LDIM 80
#define EDIM 256
#define DDIM 256
#define TDIM 20
#define NSPECIAL 4
#define NSYMB 100

// ---------------- device state (no allocation allowed) ----------------
__device__ float g_emb[(size_t)TDIM * BDIM * DDIM];   // [T,B,D]
__device__ float g_h0a[BDIM * DDIM];
__device__ float g_h0b[BDIM * DDIM];
__device__ float g_h1a[BDIM * DDIM];
__device__ float g_h1b[BDIM * DDIM];
__device__ float g_c0[BDIM * DDIM];
__device__ float g_c1[BDIM * DDIM];
__device__ float g_xc[BDIM * (DDIM + EDIM)];          // [B, 512]
__device__ float g_comb[BDIM * DDIM];
__device__ float g_z[BDIM * DDIM];

// pre-split weights: plain row-major [N][Ktot] bf16 (hi only; A carries lo)
__device__ __nv_bfloat16 g_w0hi[1024 * 512];
__device__ __nv_bfloat16 g_w1hi[1024 * 512];
__device__ __nv_bfloat16 g_wchi[256 * 512];
__device__ __nv_bfloat16 g_wohi[256 * 256];

#define SEL_XC   0
#define SEL_COMB 1
#define SEL_H0A  2
#define SEL_H0B  3
#define SEL_H1A  4
#define SEL_H1B  5
#define SEL_C0   6
#define SEL_C1   7
#define SEL_Z    8
#define SEL_W0HI 9
#define SEL_W1HI 10
#define SEL_WCHI 11
#define SEL_WOHI 12

__device__ __forceinline__ float* buf_ptr(int s) {
    switch (s) {
        case SEL_XC:   return g_xc;
        case SEL_COMB: return g_comb;
        case SEL_H0A:  return g_h0a;
        case SEL_H0B:  return g_h0b;
        case SEL_H1A:  return g_h1a;
        case SEL_H1B:  return g_h1b;
        case SEL_C0:   return g_c0;
        case SEL_C1:   return g_c1;
        case SEL_Z:    return g_z;
    }
    return nullptr;
}
__device__ __forceinline__ __nv_bfloat16* wbuf_ptr(int s) {
    switch (s) {
        case SEL_W0HI: return g_w0hi;
        case SEL_W1HI: return g_w1hi;
        case SEL_WCHI: return g_wchi;
        case SEL_WOHI: return g_wohi;
    }
    return nullptr;
}

__device__ __forceinline__ uint32_t smem_u32(const void* p) {
    uint32_t a;
    asm("{ .reg .u64 t; cvta.to.shared.u64 t, %1; cvt.u32.u64 %0, t; }" : "=r"(a) : "l"(p));
    return a;
}

__device__ __forceinline__ void ldm_x4(uint32_t* r, uint32_t addr) {
    asm volatile("ldmatrix.sync.aligned.m8n8.x4.shared.b16 {%0,%1,%2,%3}, [%4];"
                 : "=r"(r[0]), "=r"(r[1]), "=r"(r[2]), "=r"(r[3]) : "r"(addr));
}
__device__ __forceinline__ void mma_bf16(float* d, const uint32_t* a, const uint32_t* b) {
    asm volatile(
        "mma.sync.aligned.m16n8k16.row.col.f32.bf16.bf16.f32 "
        "{%0,%1,%2,%3}, {%4,%5,%6,%7}, {%8,%9}, {%0,%1,%2,%3};"
        : "+f"(d[0]), "+f"(d[1]), "+f"(d[2]), "+f"(d[3])
        : "r"(a[0]), "r"(a[1]), "r"(a[2]), "r"(a[3]), "r"(b[0]), "r"(b[1]));
}

__device__ __forceinline__ void split2(float x, float y, uint32_t& hi, uint32_t& lo) {
    __nv_bfloat16 hx = __float2bfloat16(x);
    __nv_bfloat16 hy = __float2bfloat16(y);
    __nv_bfloat16 lx = __float2bfloat16(x - __bfloat162float(hx));
    __nv_bfloat16 ly = __float2bfloat16(y - __bfloat162float(hy));
    hi = (uint32_t)__bfloat16_as_ushort(hx) | ((uint32_t)__bfloat16_as_ushort(hy) << 16);
    lo = (uint32_t)__bfloat16_as_ushort(lx) | ((uint32_t)__bfloat16_as_ushort(ly) << 16);
}

// ---- weight pre-convert: fp32 -> bf16 (round-to-nearest), row-major [N][Ktot] ----
__global__ void conv_w_kernel(const float* __restrict__ S1, int k1,
                              const float* __restrict__ S2, int k2,
                              int Ktot, int interleave, int hi_sel) {
    int idx = blockIdx.x * 256 + threadIdx.x;   // over N*Ktot
    int n = idx / Ktot;
    int k = idx - n * Ktot;
    int rs = interleave ? (((n & 3) << 8) | (n >> 2)) : n;
    float x = (k < k1) ? S1[(size_t)rs * k1 + k] : S2[(size_t)rs * k2 + (k - k1)];
    wbuf_ptr(hi_sel)[idx] = __float2bfloat16(x);
}

// ---------------- embedding precompute + state zeroing (fused) ----------------
__global__ void embed_kernel(const int* __restrict__ tgt,
                             const float* __restrict__ common,
                             const float* __restrict__ syms) {
    int idx = blockIdx.x * 256 + threadIdx.x;
    if (idx < BDIM * DDIM) {
        g_h0a[idx] = 0.f; g_h0b[idx] = 0.f;
        g_h1a[idx] = 0.f; g_h1b[idx] = 0.f;
        g_c0[idx]  = 0.f; g_c1[idx]  = 0.f;
    }
    int d  = idx & (DDIM - 1);
    int tb = idx >> 8;
    int t  = tb >> 10;
    int b  = tb & (BDIM - 1);
    int s  = tgt[b * TDIM + t];
    float v;
    if (s < NSPECIAL) {
        int si = s < 0 ? 0 : s;
        v = common[si * DDIM + d];
    } else {
        int si = s - NSPECIAL;
        if (si > NSYMB - 1) si = NSYMB - 1;
        v = syms[((size_t)b * NSYMB + si) * DDIM + d];
    }
    g_emb[idx] = v;
}

// ---------------- fused attention ----------------
__global__ __launch_bounds__(256) void attn_kernel(
    int t, int h1_sel,
    const float* __restrict__ enc,
    const float* __restrict__ W_attn,
    const float* __restrict__ b_attn)
{
    int b   = blockIdx.x;
    int tid = threadIdx.x;
    __shared__ float eh[2 * DDIM];
    __shared__ float ap[LDIM];

    const float* h1 = buf_ptr(h1_sel);
    eh[tid]        = g_emb[((size_t)t * BDIM + b) * DDIM + tid];
    eh[DDIM + tid] = h1[b * DDIM + tid];
    __syncthreads();

    int warp = tid >> 5, lane = tid & 31;
    for (int l = warp; l < LDIM; l += 8) {
        const float* wr = W_attn + l * (2 * DDIM);
        float s = 0.f;
        #pragma unroll 4
        for (int k = lane; k < 2 * DDIM; k += 32) s = fmaf(wr[k], eh[k], s);
        #pragma unroll
        for (int o = 16; o; o >>= 1) s += __shfl_xor_sync(0xffffffffu, s, o);
        if (lane == 0) ap[l] = s + b_attn[l];
    }
    __syncthreads();

    if (warp == 0) {
        float v0 = ap[lane], v1 = ap[lane + 32];
        float v2 = (lane < LDIM - 64) ? ap[lane + 64] : -1e30f;
        float m = fmaxf(fmaxf(v0, v1), v2);
        #pragma unroll
        for (int o = 16; o; o >>= 1) m = fmaxf(m, __shfl_xor_sync(0xffffffffu, m, o));
        float e0 = __expf(v0 - m), e1 = __expf(v1 - m);
        float e2 = (lane < LDIM - 64) ? __expf(v2 - m) : 0.f;
        float ssum = e0 + e1 + e2;
        #pragma unroll
        for (int o = 16; o; o >>= 1) ssum += __shfl_xor_sync(0xffffffffu, ssum, o);
        float inv = 1.f / ssum;
        ap[lane] = e0 * inv;
        ap[lane + 32] = e1 * inv;
        if (lane < LDIM - 64) ap[lane + 64] = e2 * inv;
    }
    __syncthreads();

    float acc = 0.f;
    const float* eb = enc + (size_t)b * LDIM * EDIM + tid;
    #pragma unroll 8
    for (int l = 0; l < LDIM; l++) acc = fmaf(ap[l], eb[(size_t)l * EDIM], acc);

    g_xc[b * (DDIM + EDIM) + tid]        = eh[tid];
    g_xc[b * (DDIM + EDIM) + DDIM + tid] = acc;
}

// ---- HMMA GEMM 32x64 tiles, 3 CTAs/SM, 2-pass split (Ah·Bh + Al·Bh) ----
// C[BMxBN tile] = A@W^T, A fp32 K-concat A1|A2 split hi/lo on the fly, W bf16.
// mode: 0 plain+bias, 1 relu+bias, 2 fused LSTM cell (interleaved gate cols).
#define BM 32
#define BN 64
#define KC 64
#define AST 72            // padded bf16 row stride in smem
#define GST 68            // epilogue float row stride
#define OFF_AHI 0
#define OFF_ALO 4608
#define OFF_BHI 9216
#define GSM_TOTAL 18432

__global__ __launch_bounds__(256, 3)
void gemm_mma_kernel(int a1_sel, int a1_ld, int K1,
                     int a2_sel, int a2_ld, int Ktot,
                     int whi_sel,
                     const float* __restrict__ bias1, const float* __restrict__ bias2,
                     int out_sel, int ldc, int mode, int c_sel, int h_sel)
{
    extern __shared__ __align__(16) char sm[];
    uint32_t smb = smem_u32(sm);
    int tid = threadIdx.x, wid = tid >> 5, lane = tid & 31;
    int wm = (wid & 1) * 16;          // warp M offset (2 warps over 32)
    int wn = (wid >> 1) * 16;         // warp N offset (4 warps over 64)
    int m0 = blockIdx.y * BM;
    int n0 = blockIdx.x * BN;

    const float* A1 = buf_ptr(a1_sel);
    const float* A2 = buf_ptr(a2_sel);
    const __nv_bfloat16* whi = wbuf_ptr(whi_sel) + (size_t)n0 * Ktot;

    float acc[2][4];
    #pragma unroll
    for (int j = 0; j < 2; j++)
        #pragma unroll
        for (int k = 0; k < 4; k++) acc[j][k] = 0.f;

    int nchunks = Ktot / KC;
    int arow = tid >> 3;              // 0..31, A load row
    int acb  = (tid & 7) * 8;         // col base (8 floats)
    int brow = tid >> 2;              // 0..63, B load row
    int bcb  = (tid & 3) * 16;        // col base (16 bf16)

    float4 avreg[2];
    uint4  bhreg[2];

    // prefetch chunk 0
    {
        const float* Ar = (0 < K1)
            ? A1 + (size_t)(m0 + arow) * a1_ld + acb
            : A2 + (size_t)(m0 + arow) * a2_ld + acb;
        avreg[0] = *(const float4*)(Ar + 0);
        avreg[1] = *(const float4*)(Ar + 4);
        size_t src = (size_t)brow * Ktot + bcb;
        bhreg[0] = *(const uint4*)(whi + src);
        bhreg[1] = *(const uint4*)(whi + src + 8);
    }

    for (int kc = 0; kc < nchunks; kc++) {
        // store prefetched chunk to smem (A: split on the fly)
        #pragma unroll
        for (int i = 0; i < 2; i++) {
            uint2 H, L;
            split2(avreg[i].x, avreg[i].y, H.x, L.x);
            split2(avreg[i].z, avreg[i].w, H.y, L.y);
            int off = (arow * AST + acb + i * 4) * 2;
            *(uint2*)(sm + OFF_AHI + off) = H;
            *(uint2*)(sm + OFF_ALO + off) = L;
        }
        {
            int off = (brow * AST + bcb) * 2;
            *(uint4*)(sm + OFF_BHI + off)      = bhreg[0];
            *(uint4*)(sm + OFF_BHI + off + 16) = bhreg[1];
        }
        __syncthreads();

        // prefetch next chunk (overlaps with MMA compute below)
        if (kc + 1 < nchunks) {
            int kg = (kc + 1) * KC;
            const float* Ar = (kg < K1)
                ? A1 + (size_t)(m0 + arow) * a1_ld + kg + acb
                : A2 + (size_t)(m0 + arow) * a2_ld + (kg - K1) + acb;
            avreg[0] = *(const float4*)(Ar + 0);
            avreg[1] = *(const float4*)(Ar + 4);
            size_t src = (size_t)brow * Ktot + kg + bcb;
            bhreg[0] = *(const uint4*)(whi + src);
            bhreg[1] = *(const uint4*)(whi + src + 8);
        }

        #pragma unroll
        for (int kk = 0; kk < 4; kk++) {
            int k0 = kk * 16;
            uint32_t ah[4], al[4], bh[4];
            // A m16k16 fragments (hi + lo)
            {
                int ar = wm + (lane & 15);
                int ac = k0 + ((lane >> 4) << 3);
                uint32_t ad = smb + (((ar * AST) + ac) << 1);
                ldm_x4(ah, ad + OFF_AHI);
                ldm_x4(al, ad + OFF_ALO);
            }
            // B n16k16 fragments via single x4
            {
                int brr = wn + (lane & 7) + ((lane >> 4) << 3);
                int bcc = k0 + (((lane >> 3) & 1) << 3);
                uint32_t bd = smb + (((brr * AST) + bcc) << 1);
                ldm_x4(bh, bd + OFF_BHI);
            }
            #pragma unroll
            for (int ni = 0; ni < 2; ni++) {
                mma_bf16(acc[ni], ah, bh + ni * 2);
                mma_bf16(acc[ni], al, bh + ni * 2);
            }
        }
        __syncthreads();
    }

    // stage accumulators through smem (aliases A/B buffers)
    float* gbuf = (float*)sm;
    #pragma unroll
    for (int ni = 0; ni < 2; ni++) {
        int r = wm + (lane >> 2);
        int cc = wn + ni * 8 + 2 * (lane & 3);
        *(float2*)&gbuf[r * GST + cc]       = make_float2(acc[ni][0], acc[ni][1]);
        *(float2*)&gbuf[(r + 8) * GST + cc] = make_float2(acc[ni][2], acc[ni][3]);
    }
    __syncthreads();

    if (mode == 2) {
        // BN=64 -> 16 hidden units per CTA, cols 4u..4u+3 = gates i,f,g,o
        float* cb = buf_ptr(c_sel);
        float* hb = buf_ptr(h_sel);
        #pragma unroll
        for (int i = 0; i < 2; i++) {
            int idx = tid + i * 256;          // over 32*16
            int m = idx >> 4, u = idx & 15;
            int j = (n0 >> 2) + u;
            float gi = gbuf[m * GST + 4 * u + 0] + bias1[j]       + bias2[j];
            float gf = gbuf[m * GST + 4 * u + 1] + bias1[256 + j] + bias2[256 + j];
            float gg = gbuf[m * GST + 4 * u + 2] + bias1[512 + j] + bias2[512 + j];
            float go = gbuf[m * GST + 4 * u + 3] + bias1[768 + j] + bias2[768 + j];
            float si = 1.f / (1.f + __expf(-gi));
            float sf = 1.f / (1.f + __expf(-gf));
            float so = 1.f / (1.f + __expf(-go));
            int gidx = (m0 + m) * DDIM + j;
            float ccv = sf * cb[gidx] + si * tanhf(gg);
            cb[gidx] = ccv;
            hb[gidx] = so * tanhf(ccv);
        }
    } else {
        float* C = buf_ptr(out_sel);
        #pragma unroll
        for (int i = 0; i < 2; i++) {
            int idx = tid + i * 256;          // over 32*16 float4s
            int m = idx >> 4, nq = (idx & 15) << 2;
            int n = n0 + nq;
            float4 v;
            v.x = gbuf[m * GST + nq + 0] + bias1[n + 0];
            v.y = gbuf[m * GST + nq + 1] + bias1[n + 1];
            v.z = gbuf[m * GST + nq + 2] + bias1[n + 2];
            v.w = gbuf[m * GST + nq + 3] + bias1[n + 3];
            if (mode == 1) {
                v.x = fmaxf(v.x, 0.f); v.y = fmaxf(v.y, 0.f);
                v.z = fmaxf(v.z, 0.f); v.w = fmaxf(v.w, 0.f);
            }
            *(float4*)(C + (size_t)(m0 + m) * ldc + n) = v;
        }
    }
}

// ---------------- log-softmax over 256 ----------------
__global__ __launch_bounds__(256) void logsoftmax_kernel(int t, float* __restrict__ out) {
    int b = blockIdx.x, tid = threadIdx.x;
    __shared__ float smr[256];
    float v = g_z[b * DDIM + tid];
    smr[tid] = v; __syncthreads();
    #pragma unroll
    for (int o = 128; o; o >>= 1) { if (tid < o) smr[tid] = fmaxf(smr[tid], smr[tid + o]); __syncthreads(); }
    float mx = smr[0]; __syncthreads();
    float e = __expf(v - mx);
    smr[tid] = e; __syncthreads();
    #pragma unroll
    for (int o = 128; o; o >>= 1) { if (tid < o) smr[tid] += smr[tid + o]; __syncthreads(); }
    float lse = __logf(smr[0]) + mx;
    out[((size_t)t * BDIM + b) * DDIM + tid] = v - lse;
}

// ---------------- launch ----------------
extern "C" void kernel_launch(void* const* d_in, const int* in_sizes, int n_in,
                              void* d_out, int out_size) {
    (void)in_sizes; (void)n_in; (void)out_size;
    const float* enc    = (const float*)d_in[0];
    const float* syms   = (const float*)d_in[1];
    const int*   tgt    = (const int*)d_in[2];
    const float* common = (const float*)d_in[3];
    const float* W_attn = (const float*)d_in[4];
    const float* b_attn = (const float*)d_in[5];
    const float* W_comb = (const float*)d_in[6];
    const float* b_comb = (const float*)d_in[7];
    const float* Wih0   = (const float*)d_in[8];
    const float* Whh0   = (const float*)d_in[9];
    const float* bih0   = (const float*)d_in[10];
    const float* bhh0   = (const float*)d_in[11];
    const float* Wih1   = (const float*)d_in[12];
    const float* Whh1   = (const float*)d_in[13];
    const float* bih1   = (const float*)d_in[14];
    const float* bhh1   = (const float*)d_in[15];
    const float* W_out  = (const float*)d_in[16];
    const float* b_out  = (const float*)d_in[17];
    float* out = (float*)d_out;

    cudaFuncSetAttribute(gemm_mma_kernel,
                         cudaFuncAttributeMaxDynamicSharedMemorySize, GSM_TOTAL);

    int h0_cur = SEL_H0A, h0_nxt = SEL_H0B;
    int h1_cur = SEL_H1A, h1_nxt = SEL_H1B;

    for (int t = 0; t < TDIM; t++) {
        if (t == 0) {
            // setup interleaved so launch index 5 (ncu -s 5 -c 1) = gate-0 GEMM
            embed_kernel<<<(TDIM * BDIM * DDIM) / 256, 256>>>(tgt, common, syms);  // 0
            attn_kernel<<<BDIM, 256>>>(t, h1_cur, enc, W_attn, b_attn);            // 1
            conv_w_kernel<<<(256 * 512) / 256, 256>>>(W_comb, 512, W_comb, 0, 512, 0, SEL_WCHI);  // 2
            gemm_mma_kernel<<<dim3(DDIM / BN, BDIM / BM), 256, GSM_TOTAL>>>(        // 3
                SEL_XC, 512, 512, SEL_XC, 512, 512,
                SEL_WCHI, b_comb, nullptr, SEL_COMB, 256, 1, -1, -1);
            conv_w_kernel<<<(1024 * 512) / 256, 256>>>(Wih0, 256, Whh0, 256, 512, 1, SEL_W0HI);   // 4
            gemm_mma_kernel<<<dim3(4 * DDIM / BN, BDIM / BM), 256, GSM_TOTAL>>>(    // 5 <- profiled
                SEL_COMB, 256, 256, h0_cur, 256, 512,
                SEL_W0HI, bih0, bhh0, -1, 0, 2, SEL_C0, h0_nxt);
            conv_w_kernel<<<(1024 * 512) / 256, 256>>>(Wih1, 256, Whh1, 256, 512, 1, SEL_W1HI);
            gemm_mma_kernel<<<dim3(4 * DDIM / BN, BDIM / BM), 256, GSM_TOTAL>>>(
                h0_nxt, 256, 256, h1_cur, 256, 512,
                SEL_W1HI, bih1, bhh1, -1, 0, 2, SEL_C1, h1_nxt);
            conv_w_kernel<<<(256 * 256) / 256, 256>>>(W_out, 256, W_out, 0, 256, 0, SEL_WOHI);
            gemm_mma_kernel<<<dim3(DDIM / BN, BDIM / BM), 256, GSM_TOTAL>>>(
                h1_nxt, 256, 256, h1_nxt, 256, 256,
                SEL_WOHI, b_out, nullptr, SEL_Z, 256, 0, -1, -1);
            logsoftmax_kernel<<<BDIM, 256>>>(t, out);
        } else {
            attn_kernel<<<BDIM, 256>>>(t, h1_cur, enc, W_attn, b_attn);
            gemm_mma_kernel<<<dim3(DDIM / BN, BDIM / BM), 256, GSM_TOTAL>>>(
                SEL_XC, 512, 512, SEL_XC, 512, 512,
                SEL_WCHI, b_comb, nullptr, SEL_COMB, 256, 1, -1, -1);
            gemm_mma_kernel<<<dim3(4 * DDIM / BN, BDIM / BM), 256, GSM_TOTAL>>>(
                SEL_COMB, 256, 256, h0_cur, 256, 512,
                SEL_W0HI, bih0, bhh0, -1, 0, 2, SEL_C0, h0_nxt);
            gemm_mma_kernel<<<dim3(4 * DDIM / BN, BDIM / BM), 256, GSM_TOTAL>>>(
                h0_nxt, 256, 256, h1_cur, 256, 512,
                SEL_W1HI, bih1, bhh1, -1, 0, 2, SEL_C1, h1_nxt);
            gemm_mma_kernel<<<dim3(DDIM / BN, BDIM / BM), 256, GSM_TOTAL>>>(
                h1_nxt, 256, 256, h1_nxt, 256, 256,
                SEL_WOHI, b_out, nullptr, SEL_Z, 256, 0, -1, -1);
            logsoftmax_kernel<<<BDIM, 256>>>(t, out);
        }
        int tmp;
        tmp = h0_cur; h0_cur = h0_nxt; h0_nxt = tmp;
        tmp = h1_cur; h1_cur = h1_nxt; h1_nxt = tmp;
    }
}